// round 5
// baseline (speedup 1.0000x reference)
#include <cuda_runtime.h>
#include <cuda_bf16.h>
#include <math.h>

#define N_NODES 20000
#define E_EDGES 640000
#define TOT_E   (E_EDGES + N_NODES)   // with self-loops
#define NGRAPH  64
#define F_IN    256
#define HID     128
#define HEADS   2
#define OUTF    10
#define NEG_SLOPE 0.2f

// ---------------- scratch (device globals; no allocation allowed) -----------
__device__ float g_h1  [(size_t)N_NODES * 256];   // layer1 projected features
__device__ float g_out1[(size_t)N_NODES * 256];   // layer1 output (relu)
__device__ float g_h2  [(size_t)N_NODES * 128];   // layer2 projected features
__device__ float g_out2[(size_t)N_NODES * 128];   // layer2 output
__device__ float g_al_s1[N_NODES * 2];
__device__ float g_al_d1[N_NODES * 2];
__device__ float g_al_s2[N_NODES];
__device__ float g_al_d2[N_NODES];
__device__ int   g_deg   [N_NODES];
__device__ int   g_off   [N_NODES + 1];
__device__ int   g_cursor[N_NODES];
__device__ int   g_csr_src[TOT_E];
__device__ int   g_ei    [2 * E_EDGES];           // normalized int32 edge index
__device__ int   g_batch [N_NODES];               // normalized int32 batch
__device__ int   g_is64;                          // 1 if inputs are int64

// ---------------- dtype detection + normalization ---------------------------
// If edge data is int64 (values < 2^31, >=0), every odd int32 word is 0.
// If it's int32, 256 consecutive odd words of uniform-random node ids being
// all zero has probability ~(1/20000)^256 ~ 0. So this test is exact in practice.
__global__ void detect_kernel(const int* __restrict__ raw) {
    int any = 0;
#pragma unroll 8
    for (int i = 0; i < 256; i++) any |= raw[2 * i + 1];
    g_is64 = (any == 0) ? 1 : 0;
}

__global__ void convert_edges_kernel(const int* __restrict__ raw) {
    int i = blockIdx.x * blockDim.x + threadIdx.x;
    if (i >= 2 * E_EDGES) return;
    g_ei[i] = g_is64 ? raw[2 * i] : raw[i];
}

__global__ void convert_batch_kernel(const int* __restrict__ raw) {
    int i = blockIdx.x * blockDim.x + threadIdx.x;
    if (i >= N_NODES) return;
    g_batch[i] = g_is64 ? raw[2 * i] : raw[i];
}

// ---------------- CSR construction ------------------------------------------
__global__ void zero_deg_kernel() {
    int i = blockIdx.x * blockDim.x + threadIdx.x;
    if (i < N_NODES) g_deg[i] = 0;
}

__global__ void count_kernel() {
    int i = blockIdx.x * blockDim.x + threadIdx.x;
    if (i < E_EDGES) {
        int dst = g_ei[E_EDGES + i];
        atomicAdd(&g_deg[dst], 1);
    }
}

// single-block scan over 20000 counts (+1 self loop each) -> exclusive offsets
__global__ void scan_kernel() {
    __shared__ int sh[1024];
    __shared__ int carry;
    const int T = 1024;
    int t = threadIdx.x;
    if (t == 0) carry = 0;
    __syncthreads();
    for (int base = 0; base < N_NODES; base += T) {
        int i = base + t;
        int v = (i < N_NODES) ? (g_deg[i] + 1) : 0;
        sh[t] = v;
        __syncthreads();
        for (int ofs = 1; ofs < T; ofs <<= 1) {
            int add = (t >= ofs) ? sh[t - ofs] : 0;
            __syncthreads();
            sh[t] += add;
            __syncthreads();
        }
        int incl = sh[t];
        if (i < N_NODES) {
            int ex = carry + incl - v;
            g_off[i]    = ex;
            g_cursor[i] = ex;
        }
        __syncthreads();
        if (t == T - 1) carry += incl;
        __syncthreads();
    }
    if (t == 0) g_off[N_NODES] = carry;   // == TOT_E
}

__global__ void fill_kernel() {
    int i = blockIdx.x * blockDim.x + threadIdx.x;
    if (i < E_EDGES) {
        int src = g_ei[i];
        int dst = g_ei[E_EDGES + i];
        int pos = atomicAdd(&g_cursor[dst], 1);
        g_csr_src[pos] = src;
    } else if (i < TOT_E) {
        int n = i - E_EDGES;            // self loop
        int pos = atomicAdd(&g_cursor[n], 1);
        g_csr_src[pos] = n;
    }
}

// ---------------- SGEMM: C[M x NC] = A[M x K] @ B[NC x K]^T -----------------
// BM=128, BN=128, BK=16, 256 threads, 8x8 per-thread microtile
template <int K, int NC>
__device__ __forceinline__ void sgemm_body(const float* __restrict__ A,
                                           const float* __restrict__ B,
                                           float* __restrict__ C, int M) {
    __shared__ float As[16][128];
    __shared__ float Bs[16][128];
    int tid = threadIdx.x;
    int bm = blockIdx.x * 128;
    int bn = blockIdx.y * 128;
    int tx = tid & 15;    // N dir
    int ty = tid >> 4;    // M dir
    float acc[8][8];
#pragma unroll
    for (int i = 0; i < 8; i++)
#pragma unroll
        for (int j = 0; j < 8; j++) acc[i][j] = 0.f;

    for (int k0 = 0; k0 < K; k0 += 16) {
#pragma unroll
        for (int r = 0; r < 2; r++) {
            int f = tid + r * 256;         // 512 float4 per tile
            int row = f >> 2, c4 = (f & 3) << 2;
            float4 v = make_float4(0.f, 0.f, 0.f, 0.f);
            int gr = bm + row;
            if (gr < M)
                v = *reinterpret_cast<const float4*>(A + (size_t)gr * K + k0 + c4);
            As[c4 + 0][row] = v.x; As[c4 + 1][row] = v.y;
            As[c4 + 2][row] = v.z; As[c4 + 3][row] = v.w;
        }
#pragma unroll
        for (int r = 0; r < 2; r++) {
            int f = tid + r * 256;
            int row = f >> 2, c4 = (f & 3) << 2;
            float4 v = make_float4(0.f, 0.f, 0.f, 0.f);
            int gn = bn + row;
            if (gn < NC)
                v = *reinterpret_cast<const float4*>(B + (size_t)gn * K + k0 + c4);
            Bs[c4 + 0][row] = v.x; Bs[c4 + 1][row] = v.y;
            Bs[c4 + 2][row] = v.z; Bs[c4 + 3][row] = v.w;
        }
        __syncthreads();
#pragma unroll
        for (int kk = 0; kk < 16; kk++) {
            float a[8], b[8];
#pragma unroll
            for (int i = 0; i < 8; i++) a[i] = As[kk][ty * 8 + i];
#pragma unroll
            for (int j = 0; j < 8; j++) b[j] = Bs[kk][tx * 8 + j];
#pragma unroll
            for (int i = 0; i < 8; i++)
#pragma unroll
                for (int j = 0; j < 8; j++) acc[i][j] += a[i] * b[j];
        }
        __syncthreads();
    }
#pragma unroll
    for (int i = 0; i < 8; i++) {
        int gr = bm + ty * 8 + i;
        if (gr >= M) break;
#pragma unroll
        for (int j = 0; j < 8; j += 4) {
            int gc = bn + tx * 8 + j;
            float4 v = make_float4(acc[i][j], acc[i][j + 1], acc[i][j + 2], acc[i][j + 3]);
            *reinterpret_cast<float4*>(C + (size_t)gr * NC + gc) = v;
        }
    }
}

__global__ void gemm1_kernel(const float* __restrict__ x, const float* __restrict__ W1) {
    sgemm_body<256, 256>(x, W1, g_h1, N_NODES);
}
__global__ void gemm2_kernel(const float* __restrict__ W2) {
    sgemm_body<256, 128>(g_out1, W2, g_h2, N_NODES);
}

// ---------------- attention logits (per node, per head dot products) --------
__global__ void logits1_kernel(const float* __restrict__ a_s, const float* __restrict__ a_d) {
    int w = (blockIdx.x * blockDim.x + threadIdx.x) >> 5;
    int lane = threadIdx.x & 31;
    if (w >= N_NODES * HEADS) return;
    int n = w >> 1, h = w & 1;
    const float* hp = g_h1 + (size_t)n * 256 + h * 128;
    float ss = 0.f, sd = 0.f;
#pragma unroll
    for (int q = 0; q < 4; q++) {
        int c = lane + q * 32;
        float v = hp[c];
        ss += v * a_s[h * 128 + c];
        sd += v * a_d[h * 128 + c];
    }
#pragma unroll
    for (int o = 16; o; o >>= 1) {
        ss += __shfl_xor_sync(0xffffffffu, ss, o);
        sd += __shfl_xor_sync(0xffffffffu, sd, o);
    }
    if (lane == 0) { g_al_s1[n * 2 + h] = ss; g_al_d1[n * 2 + h] = sd; }
}

__global__ void logits2_kernel(const float* __restrict__ a_s, const float* __restrict__ a_d) {
    int w = (blockIdx.x * blockDim.x + threadIdx.x) >> 5;
    int lane = threadIdx.x & 31;
    if (w >= N_NODES) return;
    const float* hp = g_h2 + (size_t)w * 128;
    float ss = 0.f, sd = 0.f;
#pragma unroll
    for (int q = 0; q < 4; q++) {
        int c = lane + q * 32;
        float v = hp[c];
        ss += v * a_s[c];
        sd += v * a_d[c];
    }
#pragma unroll
    for (int o = 16; o; o >>= 1) {
        ss += __shfl_xor_sync(0xffffffffu, ss, o);
        sd += __shfl_xor_sync(0xffffffffu, sd, o);
    }
    if (lane == 0) { g_al_s2[w] = ss; g_al_d2[w] = sd; }
}

// ---------------- aggregation layer 1: warp per (node, head) ----------------
__global__ void agg1_kernel(const float* __restrict__ b1) {
    int w = (blockIdx.x * blockDim.x + threadIdx.x) >> 5;
    int lane = threadIdx.x & 31;
    if (w >= N_NODES * HEADS) return;
    int n = w >> 1, h = w & 1;
    int beg = g_off[n], end = g_off[n + 1];
    float ald = g_al_d1[n * 2 + h];

    // pass 1: segment max
    float m = -1e30f;
    for (int i = beg + lane; i < end; i += 32) {
        int s = g_csr_src[i];
        float e = g_al_s1[s * 2 + h] + ald;
        e = (e > 0.f) ? e : e * NEG_SLOPE;
        m = fmaxf(m, e);
    }
#pragma unroll
    for (int o = 16; o; o >>= 1) m = fmaxf(m, __shfl_xor_sync(0xffffffffu, m, o));

    // pass 2: exp, denom, weighted feature accumulation (chunks of 32)
    float denom = 0.f;
    float acc0 = 0.f, acc1 = 0.f, acc2 = 0.f, acc3 = 0.f;
    for (int cbeg = beg; cbeg < end; cbeg += 32) {
        int i = cbeg + lane;
        float ex = 0.f; int s = 0;
        if (i < end) {
            s = g_csr_src[i];
            float e = g_al_s1[s * 2 + h] + ald;
            e = (e > 0.f) ? e : e * NEG_SLOPE;
            ex = __expf(e - m);
        }
        denom += ex;
        int cnt = min(32, end - cbeg);
        for (int j = 0; j < cnt; j++) {
            float exj = __shfl_sync(0xffffffffu, ex, j);
            int   sj  = __shfl_sync(0xffffffffu, s, j);
            const float* hp = g_h1 + (size_t)sj * 256 + h * 128 + lane;
            acc0 += exj * hp[0];
            acc1 += exj * hp[32];
            acc2 += exj * hp[64];
            acc3 += exj * hp[96];
        }
    }
#pragma unroll
    for (int o = 16; o; o >>= 1) denom += __shfl_xor_sync(0xffffffffu, denom, o);
    float inv = 1.0f / denom;
    float* op = g_out1 + (size_t)n * 256 + h * 128 + lane;
    const float* bp = b1 + h * 128 + lane;
    float v0 = acc0 * inv + bp[0];
    float v1 = acc1 * inv + bp[32];
    float v2 = acc2 * inv + bp[64];
    float v3 = acc3 * inv + bp[96];
    op[0]  = v0 > 0.f ? v0 : 0.f;
    op[32] = v1 > 0.f ? v1 : 0.f;
    op[64] = v2 > 0.f ? v2 : 0.f;
    op[96] = v3 > 0.f ? v3 : 0.f;
}

// ---------------- aggregation layer 2: warp per node (1 head) ---------------
__global__ void agg2_kernel(const float* __restrict__ b2) {
    int w = (blockIdx.x * blockDim.x + threadIdx.x) >> 5;
    int lane = threadIdx.x & 31;
    if (w >= N_NODES) return;
    int beg = g_off[w], end = g_off[w + 1];
    float ald = g_al_d2[w];

    float m = -1e30f;
    for (int i = beg + lane; i < end; i += 32) {
        int s = g_csr_src[i];
        float e = g_al_s2[s] + ald;
        e = (e > 0.f) ? e : e * NEG_SLOPE;
        m = fmaxf(m, e);
    }
#pragma unroll
    for (int o = 16; o; o >>= 1) m = fmaxf(m, __shfl_xor_sync(0xffffffffu, m, o));

    float denom = 0.f;
    float acc0 = 0.f, acc1 = 0.f, acc2 = 0.f, acc3 = 0.f;
    for (int cbeg = beg; cbeg < end; cbeg += 32) {
        int i = cbeg + lane;
        float ex = 0.f; int s = 0;
        if (i < end) {
            s = g_csr_src[i];
            float e = g_al_s2[s] + ald;
            e = (e > 0.f) ? e : e * NEG_SLOPE;
            ex = __expf(e - m);
        }
        denom += ex;
        int cnt = min(32, end - cbeg);
        for (int j = 0; j < cnt; j++) {
            float exj = __shfl_sync(0xffffffffu, ex, j);
            int   sj  = __shfl_sync(0xffffffffu, s, j);
            const float* hp = g_h2 + (size_t)sj * 128 + lane;
            acc0 += exj * hp[0];
            acc1 += exj * hp[32];
            acc2 += exj * hp[64];
            acc3 += exj * hp[96];
        }
    }
#pragma unroll
    for (int o = 16; o; o >>= 1) denom += __shfl_xor_sync(0xffffffffu, denom, o);
    float inv = 1.0f / denom;
    float* op = g_out2 + (size_t)w * 128 + lane;
    op[0]  = acc0 * inv + b2[lane];
    op[32] = acc1 * inv + b2[lane + 32];
    op[64] = acc2 * inv + b2[lane + 64];
    op[96] = acc3 * inv + b2[lane + 96];
}

// ---------------- mean pool per graph + prediction head ---------------------
__device__ __forceinline__ int lower_bound_i(const int* a, int n, int key) {
    int lo = 0, hi = n;
    while (lo < hi) {
        int mid = (lo + hi) >> 1;
        if (a[mid] < key) lo = mid + 1; else hi = mid;
    }
    return lo;
}

__global__ void pool_head_kernel(const float* __restrict__ Wp,
                                 const float* __restrict__ bp,
                                 float* __restrict__ out) {
    int g = blockIdx.x;
    __shared__ int s_beg, s_end;
    __shared__ float mean[128];
    if (threadIdx.x == 0) {
        s_beg = lower_bound_i(g_batch, N_NODES, g);
        s_end = lower_bound_i(g_batch, N_NODES, g + 1);
    }
    __syncthreads();
    int c = threadIdx.x;
    float acc = 0.f;
    for (int n = s_beg; n < s_end; n++) acc += g_out2[(size_t)n * 128 + c];
    float cnt = (float)max(s_end - s_beg, 1);
    mean[c] = acc / cnt;
    __syncthreads();
    if (c < OUTF) {
        float s = bp[c];
        const float* wr = Wp + c * 128;
        for (int k = 0; k < 128; k++) s += mean[k] * wr[k];
        out[g * OUTF + c] = s;
    }
}

// ---------------- launch -----------------------------------------------------
extern "C" void kernel_launch(void* const* d_in, const int* in_sizes, int n_in,
                              void* d_out, int out_size) {
    const float* x      = (const float*)d_in[0];
    const int*   ei_raw = (const int*)d_in[1];    // int32 or int64 (detected)
    const int*   b_raw  = (const int*)d_in[2];
    const float* W1     = (const float*)d_in[3];
    const float* a_src1 = (const float*)d_in[4];
    const float* a_dst1 = (const float*)d_in[5];
    const float* b1     = (const float*)d_in[6];
    const float* W2     = (const float*)d_in[7];
    const float* a_src2 = (const float*)d_in[8];
    const float* a_dst2 = (const float*)d_in[9];
    const float* b2     = (const float*)d_in[10];
    const float* Wp     = (const float*)d_in[11];
    const float* bp     = (const float*)d_in[12];
    float*       out    = (float*)d_out;

    // dtype normalization
    detect_kernel<<<1, 1>>>(ei_raw);
    convert_edges_kernel<<<(2 * E_EDGES + 255) / 256, 256>>>(ei_raw);
    convert_batch_kernel<<<(N_NODES + 255) / 256, 256>>>(b_raw);

    // CSR build
    zero_deg_kernel<<<(N_NODES + 255) / 256, 256>>>();
    count_kernel<<<(E_EDGES + 255) / 256, 256>>>();
    scan_kernel<<<1, 1024>>>();
    fill_kernel<<<(TOT_E + 255) / 256, 256>>>();

    // layer 1
    gemm1_kernel<<<dim3((N_NODES + 127) / 128, 2), 256>>>(x, W1);
    logits1_kernel<<<(N_NODES * HEADS * 32 + 255) / 256, 256>>>(a_src1, a_dst1);
    agg1_kernel<<<(N_NODES * HEADS * 32 + 255) / 256, 256>>>(b1);

    // layer 2
    gemm2_kernel<<<dim3((N_NODES + 127) / 128, 1), 256>>>(W2);
    logits2_kernel<<<(N_NODES * 32 + 255) / 256, 256>>>(a_src2, a_dst2);
    agg2_kernel<<<(N_NODES * 32 + 255) / 256, 256>>>(b2);

    // pool + head
    pool_head_kernel<<<NGRAPH, 128>>>(Wp, bp, out);
}

// round 6
// speedup vs baseline: 1.0554x; 1.0554x over previous
#include <cuda_runtime.h>
#include <cuda_bf16.h>
#include <math.h>

#define N_NODES 20000
#define E_EDGES 640000
#define TOT_E   (E_EDGES + N_NODES)   // with self-loops
#define NGRAPH  64
#define F_IN    256
#define HID     128
#define HEADS   2
#define OUTF    10
#define NEG_SLOPE 0.2f

// ---------------- scratch (device globals; no allocation allowed) -----------
__device__ float g_h1  [(size_t)N_NODES * 256];   // layer1 projected features
__device__ float g_out1[(size_t)N_NODES * 256];   // layer1 output (relu)
__device__ float g_h2  [(size_t)N_NODES * 128];   // layer2 projected features
__device__ float g_out2[(size_t)N_NODES * 128];   // layer2 output
__device__ float g_al_s1[N_NODES * 2];
__device__ float g_al_d1[N_NODES * 2];
__device__ float g_al_s2[N_NODES];
__device__ float g_al_d2[N_NODES];
__device__ int   g_deg   [N_NODES];
__device__ int   g_off   [N_NODES + 1];
__device__ int   g_cursor[N_NODES];
__device__ int   g_csr_src[TOT_E];
__device__ int   g_ei    [2 * E_EDGES];           // normalized int32 edge index
__device__ int   g_batch [N_NODES];               // normalized int32 batch

// ---------------- dtype detection helper -------------------------------------
// If edge data is int64 (values in [0, 2^31)), every odd int32 word is 0.
// For int32 uniform-random node ids, 256 consecutive odd words all zero has
// probability ~0. Computed per-block from the EDGE buffer (batch is sorted and
// could legitimately have leading zeros, so never detect from batch).
__device__ __forceinline__ int detect_is64_block(const int* __restrict__ raw_e,
                                                 int* s_flag) {
    if (threadIdx.x == 0) {
        int any = 0;
#pragma unroll 8
        for (int i = 0; i < 256; i++) any |= raw_e[2 * i + 1];
        *s_flag = (any == 0) ? 1 : 0;
    }
    __syncthreads();
    return *s_flag;
}

// ---------------- kernel 0: zero degrees + convert batch ---------------------
__global__ void prep_kernel(const int* __restrict__ raw_e,
                            const int* __restrict__ raw_b) {
    __shared__ int s_flag;
    int is64 = detect_is64_block(raw_e, &s_flag);
    int i = blockIdx.x * blockDim.x + threadIdx.x;
    if (i < N_NODES) {
        g_deg[i] = 0;
        g_batch[i] = is64 ? raw_b[2 * i] : raw_b[i];
    }
}

// ---------------- kernel 1: convert edges + count degrees --------------------
__global__ void edges_count_kernel(const int* __restrict__ raw_e) {
    __shared__ int s_flag;
    int is64 = detect_is64_block(raw_e, &s_flag);
    int i = blockIdx.x * blockDim.x + threadIdx.x;
    if (i < E_EDGES) {
        int src = is64 ? raw_e[2 * i] : raw_e[i];
        int dst = is64 ? raw_e[2 * (E_EDGES + i)] : raw_e[E_EDGES + i];
        g_ei[i] = src;
        g_ei[E_EDGES + i] = dst;
        atomicAdd(&g_deg[dst], 1);
    }
}

// ---------------- kernel 2: fast single-block scan ---------------------------
// 1024 threads; threads 0..999 each own 20 consecutive nodes (exactly 20000).
// One thread-local run + ONE 1024-wide block scan.
__global__ void scan_kernel() {
    __shared__ int sh[1024];
    int t = threadIdx.x;
    int base = t * 20;
    int vals[20];
    int tot = 0;
    if (t < 1000) {
#pragma unroll
        for (int k = 0; k < 20; k++) {
            vals[k] = g_deg[base + k] + 1;   // +1 self loop
            tot += vals[k];
        }
    }
    sh[t] = tot;
    __syncthreads();
#pragma unroll
    for (int ofs = 1; ofs < 1024; ofs <<= 1) {
        int add = (t >= ofs) ? sh[t - ofs] : 0;
        __syncthreads();
        sh[t] += add;
        __syncthreads();
    }
    int ex = sh[t] - tot;   // exclusive prefix of this thread's run
    if (t < 1000) {
        int run = ex;
#pragma unroll
        for (int k = 0; k < 20; k++) {
            g_off[base + k]    = run;
            g_cursor[base + k] = run;
            run += vals[k];
        }
    }
    if (t == 0) g_off[N_NODES] = TOT_E;
}

// ---------------- kernel 3: CSR fill -----------------------------------------
__global__ void fill_kernel() {
    int i = blockIdx.x * blockDim.x + threadIdx.x;
    if (i < E_EDGES) {
        int src = g_ei[i];
        int dst = g_ei[E_EDGES + i];
        int pos = atomicAdd(&g_cursor[dst], 1);
        g_csr_src[pos] = src;
    } else if (i < TOT_E) {
        int n = i - E_EDGES;            // self loop
        int pos = atomicAdd(&g_cursor[n], 1);
        g_csr_src[pos] = n;
    }
}

// ---------------- SGEMM + fused attention-logit epilogue ---------------------
// C[M x NC] = A[M x K] @ B[NC x K]^T. BM=BN=128, BK=16, 256 thr, 8x8 microtile.
// Each block's 128-column tile is exactly one attention head, so the per-row
// dot products with a_s/a_d reduce fully in-block via 16-lane shfl groups.
// HSTRIDE: stride between heads in the logit arrays (2 for layer1, 1 for layer2).
template <int K, int NC, int HSTRIDE>
__device__ __forceinline__ void sgemm_logits_body(const float* __restrict__ A,
                                                  const float* __restrict__ B,
                                                  float* __restrict__ C,
                                                  const float* __restrict__ a_s,
                                                  const float* __restrict__ a_d,
                                                  float* __restrict__ al_s,
                                                  float* __restrict__ al_d,
                                                  int M) {
    __shared__ float As[16][128];
    __shared__ float Bs[16][128];
    int tid = threadIdx.x;
    int bm = blockIdx.x * 128;
    int bn = blockIdx.y * 128;
    int h  = bn >> 7;                  // head index (bn is a multiple of 128)
    int tx = tid & 15;                 // N dir
    int ty = tid >> 4;                 // M dir
    float acc[8][8];
#pragma unroll
    for (int i = 0; i < 8; i++)
#pragma unroll
        for (int j = 0; j < 8; j++) acc[i][j] = 0.f;

    for (int k0 = 0; k0 < K; k0 += 16) {
#pragma unroll
        for (int r = 0; r < 2; r++) {
            int f = tid + r * 256;         // 512 float4 per tile
            int row = f >> 2, c4 = (f & 3) << 2;
            float4 v = make_float4(0.f, 0.f, 0.f, 0.f);
            int gr = bm + row;
            if (gr < M)
                v = *reinterpret_cast<const float4*>(A + (size_t)gr * K + k0 + c4);
            As[c4 + 0][row] = v.x; As[c4 + 1][row] = v.y;
            As[c4 + 2][row] = v.z; As[c4 + 3][row] = v.w;
        }
#pragma unroll
        for (int r = 0; r < 2; r++) {
            int f = tid + r * 256;
            int row = f >> 2, c4 = (f & 3) << 2;
            float4 v = make_float4(0.f, 0.f, 0.f, 0.f);
            int gn = bn + row;
            if (gn < NC)
                v = *reinterpret_cast<const float4*>(B + (size_t)gn * K + k0 + c4);
            Bs[c4 + 0][row] = v.x; Bs[c4 + 1][row] = v.y;
            Bs[c4 + 2][row] = v.z; Bs[c4 + 3][row] = v.w;
        }
        __syncthreads();
#pragma unroll
        for (int kk = 0; kk < 16; kk++) {
            float a[8], b[8];
#pragma unroll
            for (int i = 0; i < 8; i++) a[i] = As[kk][ty * 8 + i];
#pragma unroll
            for (int j = 0; j < 8; j++) b[j] = Bs[kk][tx * 8 + j];
#pragma unroll
            for (int i = 0; i < 8; i++)
#pragma unroll
                for (int j = 0; j < 8; j++) acc[i][j] += a[i] * b[j];
        }
        __syncthreads();
    }

    // store C tile
#pragma unroll
    for (int i = 0; i < 8; i++) {
        int gr = bm + ty * 8 + i;
        if (gr < M) {
#pragma unroll
            for (int j = 0; j < 8; j += 4) {
                int gc = bn + tx * 8 + j;
                float4 v = make_float4(acc[i][j], acc[i][j + 1], acc[i][j + 2], acc[i][j + 3]);
                *reinterpret_cast<float4*>(C + (size_t)gr * NC + gc) = v;
            }
        }
    }

    // fused logits: per-row dot with a_s / a_d for this head's 128 columns.
    float as_reg[8], ad_reg[8];
#pragma unroll
    for (int j = 0; j < 8; j++) {
        as_reg[j] = a_s[h * 128 + tx * 8 + j];
        ad_reg[j] = a_d[h * 128 + tx * 8 + j];
    }
#pragma unroll
    for (int i = 0; i < 8; i++) {
        float ps = 0.f, pd = 0.f;
#pragma unroll
        for (int j = 0; j < 8; j++) {
            ps += acc[i][j] * as_reg[j];
            pd += acc[i][j] * ad_reg[j];
        }
        // reduce over the 16 tx lanes; lanes sharing ty form contiguous 16-lane
        // halves of the warp (tid = ty*16+tx), so xor-shfl 8,4,2,1 stays inside.
#pragma unroll
        for (int o = 8; o; o >>= 1) {
            ps += __shfl_xor_sync(0xffffffffu, ps, o);
            pd += __shfl_xor_sync(0xffffffffu, pd, o);
        }
        if (tx == 0) {
            int gr = bm + ty * 8 + i;
            if (gr < M) {
                al_s[gr * HSTRIDE + h] = ps;
                al_d[gr * HSTRIDE + h] = pd;
            }
        }
    }
}

__global__ void gemm1_kernel(const float* __restrict__ x, const float* __restrict__ W1,
                             const float* __restrict__ a_s, const float* __restrict__ a_d) {
    sgemm_logits_body<256, 256, 2>(x, W1, g_h1, a_s, a_d, g_al_s1, g_al_d1, N_NODES);
}
__global__ void gemm2_kernel(const float* __restrict__ W2,
                             const float* __restrict__ a_s, const float* __restrict__ a_d) {
    sgemm_logits_body<256, 128, 1>(g_out1, W2, g_h2, a_s, a_d, g_al_s2, g_al_d2, N_NODES);
}

// ---------------- aggregation layer 1: warp per node, BOTH heads -------------
// Per edge: 1 CSR read, 3 shfls, 2 x LDG.128 (float4/lane) covering all 256
// source features; 8 FFMAs.
__global__ void agg1_kernel(const float* __restrict__ b1) {
    int w = (blockIdx.x * blockDim.x + threadIdx.x) >> 5;
    int lane = threadIdx.x & 31;
    if (w >= N_NODES) return;
    int beg = g_off[w], end = g_off[w + 1];
    float2 ald = *reinterpret_cast<const float2*>(&g_al_d1[w * 2]);

    // pass 1: per-head segment max
    float m0 = -1e30f, m1 = -1e30f;
    for (int i = beg + lane; i < end; i += 32) {
        int s = g_csr_src[i];
        float2 als = *reinterpret_cast<const float2*>(&g_al_s1[s * 2]);
        float e0 = als.x + ald.x; e0 = (e0 > 0.f) ? e0 : e0 * NEG_SLOPE;
        float e1 = als.y + ald.y; e1 = (e1 > 0.f) ? e1 : e1 * NEG_SLOPE;
        m0 = fmaxf(m0, e0); m1 = fmaxf(m1, e1);
    }
#pragma unroll
    for (int o = 16; o; o >>= 1) {
        m0 = fmaxf(m0, __shfl_xor_sync(0xffffffffu, m0, o));
        m1 = fmaxf(m1, __shfl_xor_sync(0xffffffffu, m1, o));
    }

    // pass 2: exp weights + weighted feature accumulation
    float d0 = 0.f, d1 = 0.f;
    float4 A0 = make_float4(0.f, 0.f, 0.f, 0.f);
    float4 A1 = make_float4(0.f, 0.f, 0.f, 0.f);
    for (int cbeg = beg; cbeg < end; cbeg += 32) {
        int i = cbeg + lane;
        float ex0 = 0.f, ex1 = 0.f; int s = 0;
        if (i < end) {
            s = g_csr_src[i];
            float2 als = *reinterpret_cast<const float2*>(&g_al_s1[s * 2]);
            float e0 = als.x + ald.x; e0 = (e0 > 0.f) ? e0 : e0 * NEG_SLOPE;
            float e1 = als.y + ald.y; e1 = (e1 > 0.f) ? e1 : e1 * NEG_SLOPE;
            ex0 = __expf(e0 - m0);
            ex1 = __expf(e1 - m1);
        }
        d0 += ex0; d1 += ex1;
        int cnt = min(32, end - cbeg);
        for (int j = 0; j < cnt; j++) {
            int   sj = __shfl_sync(0xffffffffu, s, j);
            float x0 = __shfl_sync(0xffffffffu, ex0, j);
            float x1 = __shfl_sync(0xffffffffu, ex1, j);
            const float4* hp = reinterpret_cast<const float4*>(g_h1 + (size_t)sj * 256);
            float4 v0 = hp[lane];        // head0: cols lane*4..lane*4+3
            float4 v1 = hp[32 + lane];   // head1: cols 128+lane*4..
            A0.x += x0 * v0.x; A0.y += x0 * v0.y; A0.z += x0 * v0.z; A0.w += x0 * v0.w;
            A1.x += x1 * v1.x; A1.y += x1 * v1.y; A1.z += x1 * v1.z; A1.w += x1 * v1.w;
        }
    }
#pragma unroll
    for (int o = 16; o; o >>= 1) {
        d0 += __shfl_xor_sync(0xffffffffu, d0, o);
        d1 += __shfl_xor_sync(0xffffffffu, d1, o);
    }
    float inv0 = 1.0f / d0, inv1 = 1.0f / d1;
    const float4* bq = reinterpret_cast<const float4*>(b1);
    float4 B0 = bq[lane], B1 = bq[32 + lane];
    float4 o0, o1;
    o0.x = fmaxf(A0.x * inv0 + B0.x, 0.f); o0.y = fmaxf(A0.y * inv0 + B0.y, 0.f);
    o0.z = fmaxf(A0.z * inv0 + B0.z, 0.f); o0.w = fmaxf(A0.w * inv0 + B0.w, 0.f);
    o1.x = fmaxf(A1.x * inv1 + B1.x, 0.f); o1.y = fmaxf(A1.y * inv1 + B1.y, 0.f);
    o1.z = fmaxf(A1.z * inv1 + B1.z, 0.f); o1.w = fmaxf(A1.w * inv1 + B1.w, 0.f);
    float4* op = reinterpret_cast<float4*>(g_out1 + (size_t)w * 256);
    op[lane]      = o0;
    op[32 + lane] = o1;
}

// ---------------- aggregation layer 2: warp per node (1 head) ----------------
__global__ void agg2_kernel(const float* __restrict__ b2) {
    int w = (blockIdx.x * blockDim.x + threadIdx.x) >> 5;
    int lane = threadIdx.x & 31;
    if (w >= N_NODES) return;
    int beg = g_off[w], end = g_off[w + 1];
    float ald = g_al_d2[w];

    float m = -1e30f;
    for (int i = beg + lane; i < end; i += 32) {
        int s = g_csr_src[i];
        float e = g_al_s2[s] + ald;
        e = (e > 0.f) ? e : e * NEG_SLOPE;
        m = fmaxf(m, e);
    }
#pragma unroll
    for (int o = 16; o; o >>= 1) m = fmaxf(m, __shfl_xor_sync(0xffffffffu, m, o));

    float d = 0.f;
    float4 A = make_float4(0.f, 0.f, 0.f, 0.f);
    for (int cbeg = beg; cbeg < end; cbeg += 32) {
        int i = cbeg + lane;
        float ex = 0.f; int s = 0;
        if (i < end) {
            s = g_csr_src[i];
            float e = g_al_s2[s] + ald;
            e = (e > 0.f) ? e : e * NEG_SLOPE;
            ex = __expf(e - m);
        }
        d += ex;
        int cnt = min(32, end - cbeg);
        for (int j = 0; j < cnt; j++) {
            int   sj = __shfl_sync(0xffffffffu, s, j);
            float xv = __shfl_sync(0xffffffffu, ex, j);
            const float4* hp = reinterpret_cast<const float4*>(g_h2 + (size_t)sj * 128);
            float4 v = hp[lane];
            A.x += xv * v.x; A.y += xv * v.y; A.z += xv * v.z; A.w += xv * v.w;
        }
    }
#pragma unroll
    for (int o = 16; o; o >>= 1) d += __shfl_xor_sync(0xffffffffu, d, o);
    float inv = 1.0f / d;
    const float4* bq = reinterpret_cast<const float4*>(b2);
    float4 B = bq[lane];
    float4 o4;
    o4.x = A.x * inv + B.x; o4.y = A.y * inv + B.y;
    o4.z = A.z * inv + B.z; o4.w = A.w * inv + B.w;
    reinterpret_cast<float4*>(g_out2 + (size_t)w * 128)[lane] = o4;
}

// ---------------- mean pool per graph + prediction head ---------------------
__device__ __forceinline__ int lower_bound_i(const int* a, int n, int key) {
    int lo = 0, hi = n;
    while (lo < hi) {
        int mid = (lo + hi) >> 1;
        if (a[mid] < key) lo = mid + 1; else hi = mid;
    }
    return lo;
}

__global__ void pool_head_kernel(const float* __restrict__ Wp,
                                 const float* __restrict__ bp,
                                 float* __restrict__ out) {
    int g = blockIdx.x;
    __shared__ int s_beg, s_end;
    __shared__ float mean[128];
    if (threadIdx.x == 0) {
        s_beg = lower_bound_i(g_batch, N_NODES, g);
        s_end = lower_bound_i(g_batch, N_NODES, g + 1);
    }
    __syncthreads();
    int c = threadIdx.x;
    float acc = 0.f;
    for (int n = s_beg; n < s_end; n++) acc += g_out2[(size_t)n * 128 + c];
    float cnt = (float)max(s_end - s_beg, 1);
    mean[c] = acc / cnt;
    __syncthreads();
    if (c < OUTF) {
        float s = bp[c];
        const float* wr = Wp + c * 128;
#pragma unroll 8
        for (int k = 0; k < 128; k++) s += mean[k] * wr[k];
        out[g * OUTF + c] = s;
    }
}

// ---------------- launch -----------------------------------------------------
extern "C" void kernel_launch(void* const* d_in, const int* in_sizes, int n_in,
                              void* d_out, int out_size) {
    const float* x      = (const float*)d_in[0];
    const int*   ei_raw = (const int*)d_in[1];    // int32 or int64 (detected)
    const int*   b_raw  = (const int*)d_in[2];
    const float* W1     = (const float*)d_in[3];
    const float* a_src1 = (const float*)d_in[4];
    const float* a_dst1 = (const float*)d_in[5];
    const float* b1     = (const float*)d_in[6];
    const float* W2     = (const float*)d_in[7];
    const float* a_src2 = (const float*)d_in[8];
    const float* a_dst2 = (const float*)d_in[9];
    const float* b2     = (const float*)d_in[10];
    const float* Wp     = (const float*)d_in[11];
    const float* bp     = (const float*)d_in[12];
    float*       out    = (float*)d_out;

    // 0: zero degrees + batch normalize
    prep_kernel<<<(N_NODES + 255) / 256, 256>>>(ei_raw, b_raw);
    // 1: edge normalize + degree count
    edges_count_kernel<<<(E_EDGES + 255) / 256, 256>>>(ei_raw);
    // 2: offsets
    scan_kernel<<<1, 1024>>>();
    // 3: CSR fill
    fill_kernel<<<(TOT_E + 255) / 256, 256>>>();

    // 4: layer1 GEMM + logits
    gemm1_kernel<<<dim3((N_NODES + 127) / 128, 2), 256>>>(x, W1, a_src1, a_dst1);
    // 5: layer1 aggregation (both heads per warp)
    agg1_kernel<<<(N_NODES * 32 + 255) / 256, 256>>>(b1);

    // 6: layer2 GEMM + logits
    gemm2_kernel<<<dim3((N_NODES + 127) / 128, 1), 256>>>(W2, a_src2, a_dst2);
    // 7: layer2 aggregation
    agg2_kernel<<<(N_NODES * 32 + 255) / 256, 256>>>(b2);

    // 8: pool + head
    pool_head_kernel<<<NGRAPH, 128>>>(Wp, bp, out);
}

// round 7
// speedup vs baseline: 1.1407x; 1.0809x over previous
#include <cuda_runtime.h>
#include <cuda_bf16.h>
#include <math.h>

#define N_NODES 20000
#define E_EDGES 640000
#define TOT_E   (E_EDGES + N_NODES)   // with self-loops
#define NGRAPH  64
#define F_IN    256
#define HID     128
#define HEADS   2
#define OUTF    10
#define NEG_SLOPE 0.2f

// ---------------- scratch (device globals; no allocation allowed) -----------
__device__ float g_h1  [(size_t)N_NODES * 256];   // layer1 projected features
__device__ float g_out1[(size_t)N_NODES * 256];   // layer1 output (relu)
__device__ float g_h2  [(size_t)N_NODES * 128];   // layer2 projected features
__device__ float g_out2[(size_t)N_NODES * 128];   // layer2 output
__device__ float g_al_s1[N_NODES * 2];
__device__ float g_al_d1[N_NODES * 2];
__device__ float g_al_s2[N_NODES];
__device__ float g_al_d2[N_NODES];
__device__ int   g_deg   [N_NODES];
__device__ int   g_off   [N_NODES + 1];
__device__ int   g_csr_src[TOT_E];
__device__ int   g_ei    [2 * E_EDGES];           // normalized int32 edge index
__device__ int   g_rank  [E_EDGES];               // per-edge rank within its dst
__device__ int   g_batch [N_NODES];               // normalized int32 batch

// ---------------- dtype detection helper -------------------------------------
// If edge data is int64 (values in [0, 2^31)), every odd int32 word is 0.
// For int32 uniform-random node ids, 256 consecutive odd words all zero has
// probability ~0. Computed from the EDGE buffer only (batch is sorted and can
// legitimately start with zeros).
__device__ __forceinline__ int detect_is64_block(const int* __restrict__ raw_e,
                                                 int* s_flag) {
    if (threadIdx.x == 0) {
        int any = 0;
#pragma unroll 8
        for (int i = 0; i < 256; i++) any |= raw_e[2 * i + 1];
        *s_flag = (any == 0) ? 1 : 0;
    }
    __syncthreads();
    return *s_flag;
}

// ---------------- kernel 0: zero degrees + convert batch ---------------------
__global__ void prep_kernel(const int* __restrict__ raw_e,
                            const int* __restrict__ raw_b) {
    __shared__ int s_flag;
    int is64 = detect_is64_block(raw_e, &s_flag);
    int i = blockIdx.x * blockDim.x + threadIdx.x;
    if (i < N_NODES) {
        g_deg[i] = 0;
        g_batch[i] = is64 ? raw_b[2 * i] : raw_b[i];
    }
}

// ---------------- kernel 1: convert edges + count degrees + capture rank -----
__global__ void edges_count_kernel(const int* __restrict__ raw_e) {
    __shared__ int s_flag;
    int is64 = detect_is64_block(raw_e, &s_flag);
    int i = blockIdx.x * blockDim.x + threadIdx.x;
    if (i < E_EDGES) {
        int src = is64 ? raw_e[2 * i] : raw_e[i];
        int dst = is64 ? raw_e[2 * (E_EDGES + i)] : raw_e[E_EDGES + i];
        g_ei[i] = src;
        g_ei[E_EDGES + i] = dst;
        g_rank[i] = atomicAdd(&g_deg[dst], 1);   // rank = slot within dst bucket
    }
}

// ---------------- kernel 2: fast single-block scan ---------------------------
// 1024 threads; threads 0..999 each own 20 consecutive nodes (exactly 20000).
__global__ void scan_kernel() {
    __shared__ int sh[1024];
    int t = threadIdx.x;
    int base = t * 20;
    int vals[20];
    int tot = 0;
    if (t < 1000) {
#pragma unroll
        for (int k = 0; k < 20; k++) {
            vals[k] = g_deg[base + k] + 1;   // +1 self loop
            tot += vals[k];
        }
    }
    sh[t] = tot;
    __syncthreads();
#pragma unroll
    for (int ofs = 1; ofs < 1024; ofs <<= 1) {
        int add = (t >= ofs) ? sh[t - ofs] : 0;
        __syncthreads();
        sh[t] += add;
        __syncthreads();
    }
    int ex = sh[t] - tot;   // exclusive prefix of this thread's run
    if (t < 1000) {
        int run = ex;
#pragma unroll
        for (int k = 0; k < 20; k++) {
            g_off[base + k] = run;
            run += vals[k];
        }
    }
    if (t == 0) g_off[N_NODES] = TOT_E;
}

// ---------------- kernel 3: CSR fill (atomic-free) ---------------------------
__global__ void fill_kernel() {
    int i = blockIdx.x * blockDim.x + threadIdx.x;
    if (i < E_EDGES) {
        int src = g_ei[i];
        int dst = g_ei[E_EDGES + i];
        g_csr_src[g_off[dst] + g_rank[i]] = src;
    } else if (i < TOT_E) {
        int n = i - E_EDGES;            // self loop goes last in its bucket
        g_csr_src[g_off[n] + g_deg[n]] = n;
    }
}

// ---------------- SGEMM + fused attention-logit epilogue ---------------------
// C[M x NC] = A[M x K] @ B[NC x K]^T. BM=BN=128, BK=16, 256 thr, 8x8 microtile.
// Register-prefetch double buffering: next k-slice loads overlap compute.
// Each block's 128-col tile is one attention head; per-row a_s/a_d dots reduce
// in-block via 16-lane shfl groups.
template <int K, int NC, int HSTRIDE>
__device__ __forceinline__ void sgemm_logits_body(const float* __restrict__ A,
                                                  const float* __restrict__ B,
                                                  float* __restrict__ C,
                                                  const float* __restrict__ a_s,
                                                  const float* __restrict__ a_d,
                                                  float* __restrict__ al_s,
                                                  float* __restrict__ al_d,
                                                  int M) {
    __shared__ float As[16][128];
    __shared__ float Bs[16][128];
    int tid = threadIdx.x;
    int bm = blockIdx.x * 128;
    int bn = blockIdx.y * 128;
    int h  = bn >> 7;
    int tx = tid & 15;
    int ty = tid >> 4;

    // per-thread load coords (two float4 loads per tile per array)
    int rowA0 = tid >> 2,            c4A0 = (tid & 3) << 2;
    int rowA1 = (tid + 256) >> 2,    c4A1 = ((tid + 256) & 3) << 2;

    float acc[8][8];
#pragma unroll
    for (int i = 0; i < 8; i++)
#pragma unroll
        for (int j = 0; j < 8; j++) acc[i][j] = 0.f;

    auto ldA = [&](int k0, int row, int c4) -> float4 {
        int gr = bm + row;
        if (gr < M) return *reinterpret_cast<const float4*>(A + (size_t)gr * K + k0 + c4);
        return make_float4(0.f, 0.f, 0.f, 0.f);
    };
    auto ldB = [&](int k0, int row, int c4) -> float4 {
        int gn = bn + row;
        if (gn < NC) return *reinterpret_cast<const float4*>(B + (size_t)gn * K + k0 + c4);
        return make_float4(0.f, 0.f, 0.f, 0.f);
    };
    auto stTile = [&](float4 a0, float4 a1, float4 b0, float4 b1) {
        As[c4A0 + 0][rowA0] = a0.x; As[c4A0 + 1][rowA0] = a0.y;
        As[c4A0 + 2][rowA0] = a0.z; As[c4A0 + 3][rowA0] = a0.w;
        As[c4A1 + 0][rowA1] = a1.x; As[c4A1 + 1][rowA1] = a1.y;
        As[c4A1 + 2][rowA1] = a1.z; As[c4A1 + 3][rowA1] = a1.w;
        Bs[c4A0 + 0][rowA0] = b0.x; Bs[c4A0 + 1][rowA0] = b0.y;
        Bs[c4A0 + 2][rowA0] = b0.z; Bs[c4A0 + 3][rowA0] = b0.w;
        Bs[c4A1 + 0][rowA1] = b1.x; Bs[c4A1 + 1][rowA1] = b1.y;
        Bs[c4A1 + 2][rowA1] = b1.z; Bs[c4A1 + 3][rowA1] = b1.w;
    };

    // prologue: tile 0 into smem
    {
        float4 a0 = ldA(0, rowA0, c4A0), a1 = ldA(0, rowA1, c4A1);
        float4 b0 = ldB(0, rowA0, c4A0), b1 = ldB(0, rowA1, c4A1);
        stTile(a0, a1, b0, b1);
    }
    __syncthreads();

    for (int k0 = 0; k0 < K; k0 += 16) {
        float4 na0, na1, nb0, nb1;
        bool has_next = (k0 + 16) < K;
        if (has_next) {
            na0 = ldA(k0 + 16, rowA0, c4A0); na1 = ldA(k0 + 16, rowA1, c4A1);
            nb0 = ldB(k0 + 16, rowA0, c4A0); nb1 = ldB(k0 + 16, rowA1, c4A1);
        }
#pragma unroll
        for (int kk = 0; kk < 16; kk++) {
            float a[8], b[8];
#pragma unroll
            for (int i = 0; i < 8; i++) a[i] = As[kk][ty * 8 + i];
#pragma unroll
            for (int j = 0; j < 8; j++) b[j] = Bs[kk][tx * 8 + j];
#pragma unroll
            for (int i = 0; i < 8; i++)
#pragma unroll
                for (int j = 0; j < 8; j++) acc[i][j] += a[i] * b[j];
        }
        __syncthreads();
        if (has_next) {
            stTile(na0, na1, nb0, nb1);
            __syncthreads();
        }
    }

    // store C tile
#pragma unroll
    for (int i = 0; i < 8; i++) {
        int gr = bm + ty * 8 + i;
        if (gr < M) {
#pragma unroll
            for (int j = 0; j < 8; j += 4) {
                int gc = bn + tx * 8 + j;
                float4 v = make_float4(acc[i][j], acc[i][j + 1], acc[i][j + 2], acc[i][j + 3]);
                *reinterpret_cast<float4*>(C + (size_t)gr * NC + gc) = v;
            }
        }
    }

    // fused logits
    float as_reg[8], ad_reg[8];
#pragma unroll
    for (int j = 0; j < 8; j++) {
        as_reg[j] = a_s[h * 128 + tx * 8 + j];
        ad_reg[j] = a_d[h * 128 + tx * 8 + j];
    }
#pragma unroll
    for (int i = 0; i < 8; i++) {
        float ps = 0.f, pd = 0.f;
#pragma unroll
        for (int j = 0; j < 8; j++) {
            ps += acc[i][j] * as_reg[j];
            pd += acc[i][j] * ad_reg[j];
        }
#pragma unroll
        for (int o = 8; o; o >>= 1) {
            ps += __shfl_xor_sync(0xffffffffu, ps, o);
            pd += __shfl_xor_sync(0xffffffffu, pd, o);
        }
        if (tx == 0) {
            int gr = bm + ty * 8 + i;
            if (gr < M) {
                al_s[gr * HSTRIDE + h] = ps;
                al_d[gr * HSTRIDE + h] = pd;
            }
        }
    }
}

__global__ void gemm1_kernel(const float* __restrict__ x, const float* __restrict__ W1,
                             const float* __restrict__ a_s, const float* __restrict__ a_d) {
    sgemm_logits_body<256, 256, 2>(x, W1, g_h1, a_s, a_d, g_al_s1, g_al_d1, N_NODES);
}
__global__ void gemm2_kernel(const float* __restrict__ W2,
                             const float* __restrict__ a_s, const float* __restrict__ a_d) {
    sgemm_logits_body<256, 128, 1>(g_out1, W2, g_h2, a_s, a_d, g_al_s2, g_al_d2, N_NODES);
}

// ---------------- aggregation layer 1: warp per node, BOTH heads -------------
// Single pass (no max-shift; logits are bounded ~|e|<6, exp is safe in fp32 and
// softmax is shift-invariant so the result is mathematically identical).
// Inner broadcast loop unrolled by 8 to expose 16 independent LDG.128s.
__global__ void agg1_kernel(const float* __restrict__ b1) {
    int w = (blockIdx.x * blockDim.x + threadIdx.x) >> 5;
    int lane = threadIdx.x & 31;
    if (w >= N_NODES) return;
    int beg = g_off[w], end = g_off[w + 1];
    float2 ald = *reinterpret_cast<const float2*>(&g_al_d1[w * 2]);

    float d0 = 0.f, d1 = 0.f;
    float4 A0 = make_float4(0.f, 0.f, 0.f, 0.f);
    float4 A1 = make_float4(0.f, 0.f, 0.f, 0.f);
    for (int cbeg = beg; cbeg < end; cbeg += 32) {
        int i = cbeg + lane;
        float ex0 = 0.f, ex1 = 0.f; int s = 0;
        if (i < end) {
            s = g_csr_src[i];
            float2 als = *reinterpret_cast<const float2*>(&g_al_s1[s * 2]);
            float e0 = als.x + ald.x; e0 = (e0 > 0.f) ? e0 : e0 * NEG_SLOPE;
            float e1 = als.y + ald.y; e1 = (e1 > 0.f) ? e1 : e1 * NEG_SLOPE;
            ex0 = __expf(e0);
            ex1 = __expf(e1);
        }
        d0 += ex0; d1 += ex1;
        int cnt = min(32, end - cbeg);
        int j = 0;
        for (; j + 8 <= cnt; j += 8) {
#pragma unroll
            for (int u = 0; u < 8; u++) {
                int   sj = __shfl_sync(0xffffffffu, s,   j + u);
                float x0 = __shfl_sync(0xffffffffu, ex0, j + u);
                float x1 = __shfl_sync(0xffffffffu, ex1, j + u);
                const float4* hp = reinterpret_cast<const float4*>(g_h1 + (size_t)sj * 256);
                float4 v0 = hp[lane];
                float4 v1 = hp[32 + lane];
                A0.x += x0 * v0.x; A0.y += x0 * v0.y; A0.z += x0 * v0.z; A0.w += x0 * v0.w;
                A1.x += x1 * v1.x; A1.y += x1 * v1.y; A1.z += x1 * v1.z; A1.w += x1 * v1.w;
            }
        }
        for (; j < cnt; j++) {
            int   sj = __shfl_sync(0xffffffffu, s,   j);
            float x0 = __shfl_sync(0xffffffffu, ex0, j);
            float x1 = __shfl_sync(0xffffffffu, ex1, j);
            const float4* hp = reinterpret_cast<const float4*>(g_h1 + (size_t)sj * 256);
            float4 v0 = hp[lane];
            float4 v1 = hp[32 + lane];
            A0.x += x0 * v0.x; A0.y += x0 * v0.y; A0.z += x0 * v0.z; A0.w += x0 * v0.w;
            A1.x += x1 * v1.x; A1.y += x1 * v1.y; A1.z += x1 * v1.z; A1.w += x1 * v1.w;
        }
    }
#pragma unroll
    for (int o = 16; o; o >>= 1) {
        d0 += __shfl_xor_sync(0xffffffffu, d0, o);
        d1 += __shfl_xor_sync(0xffffffffu, d1, o);
    }
    float inv0 = 1.0f / d0, inv1 = 1.0f / d1;
    const float4* bq = reinterpret_cast<const float4*>(b1);
    float4 B0 = bq[lane], B1 = bq[32 + lane];
    float4 o0, o1;
    o0.x = fmaxf(A0.x * inv0 + B0.x, 0.f); o0.y = fmaxf(A0.y * inv0 + B0.y, 0.f);
    o0.z = fmaxf(A0.z * inv0 + B0.z, 0.f); o0.w = fmaxf(A0.w * inv0 + B0.w, 0.f);
    o1.x = fmaxf(A1.x * inv1 + B1.x, 0.f); o1.y = fmaxf(A1.y * inv1 + B1.y, 0.f);
    o1.z = fmaxf(A1.z * inv1 + B1.z, 0.f); o1.w = fmaxf(A1.w * inv1 + B1.w, 0.f);
    float4* op = reinterpret_cast<float4*>(g_out1 + (size_t)w * 256);
    op[lane]      = o0;
    op[32 + lane] = o1;
}

// ---------------- aggregation layer 2: warp per node (1 head) ----------------
__global__ void agg2_kernel(const float* __restrict__ b2) {
    int w = (blockIdx.x * blockDim.x + threadIdx.x) >> 5;
    int lane = threadIdx.x & 31;
    if (w >= N_NODES) return;
    int beg = g_off[w], end = g_off[w + 1];
    float ald = g_al_d2[w];

    float d = 0.f;
    float4 A = make_float4(0.f, 0.f, 0.f, 0.f);
    for (int cbeg = beg; cbeg < end; cbeg += 32) {
        int i = cbeg + lane;
        float ex = 0.f; int s = 0;
        if (i < end) {
            s = g_csr_src[i];
            float e = g_al_s2[s] + ald;
            e = (e > 0.f) ? e : e * NEG_SLOPE;
            ex = __expf(e);
        }
        d += ex;
        int cnt = min(32, end - cbeg);
        int j = 0;
        for (; j + 8 <= cnt; j += 8) {
#pragma unroll
            for (int u = 0; u < 8; u++) {
                int   sj = __shfl_sync(0xffffffffu, s,  j + u);
                float xv = __shfl_sync(0xffffffffu, ex, j + u);
                const float4* hp = reinterpret_cast<const float4*>(g_h2 + (size_t)sj * 128);
                float4 v = hp[lane];
                A.x += xv * v.x; A.y += xv * v.y; A.z += xv * v.z; A.w += xv * v.w;
            }
        }
        for (; j < cnt; j++) {
            int   sj = __shfl_sync(0xffffffffu, s,  j);
            float xv = __shfl_sync(0xffffffffu, ex, j);
            const float4* hp = reinterpret_cast<const float4*>(g_h2 + (size_t)sj * 128);
            float4 v = hp[lane];
            A.x += xv * v.x; A.y += xv * v.y; A.z += xv * v.z; A.w += xv * v.w;
        }
    }
#pragma unroll
    for (int o = 16; o; o >>= 1) d += __shfl_xor_sync(0xffffffffu, d, o);
    float inv = 1.0f / d;
    const float4* bq = reinterpret_cast<const float4*>(b2);
    float4 B = bq[lane];
    float4 o4;
    o4.x = A.x * inv + B.x; o4.y = A.y * inv + B.y;
    o4.z = A.z * inv + B.z; o4.w = A.w * inv + B.w;
    reinterpret_cast<float4*>(g_out2 + (size_t)w * 128)[lane] = o4;
}

// ---------------- mean pool per graph + prediction head ---------------------
__device__ __forceinline__ int lower_bound_i(const int* a, int n, int key) {
    int lo = 0, hi = n;
    while (lo < hi) {
        int mid = (lo + hi) >> 1;
        if (a[mid] < key) lo = mid + 1; else hi = mid;
    }
    return lo;
}

__global__ void pool_head_kernel(const float* __restrict__ Wp,
                                 const float* __restrict__ bp,
                                 float* __restrict__ out) {
    int g = blockIdx.x;
    __shared__ int s_beg, s_end;
    __shared__ float mean[128];
    if (threadIdx.x == 0) {
        s_beg = lower_bound_i(g_batch, N_NODES, g);
        s_end = lower_bound_i(g_batch, N_NODES, g + 1);
    }
    __syncthreads();
    int c = threadIdx.x;
    float acc = 0.f;
    for (int n = s_beg; n < s_end; n++) acc += g_out2[(size_t)n * 128 + c];
    float cnt = (float)max(s_end - s_beg, 1);
    mean[c] = acc / cnt;
    __syncthreads();
    if (c < OUTF) {
        float s = bp[c];
        const float* wr = Wp + c * 128;
#pragma unroll 8
        for (int k = 0; k < 128; k++) s += mean[k] * wr[k];
        out[g * OUTF + c] = s;
    }
}

// ---------------- launch -----------------------------------------------------
extern "C" void kernel_launch(void* const* d_in, const int* in_sizes, int n_in,
                              void* d_out, int out_size) {
    const float* x      = (const float*)d_in[0];
    const int*   ei_raw = (const int*)d_in[1];    // int32 or int64 (detected)
    const int*   b_raw  = (const int*)d_in[2];
    const float* W1     = (const float*)d_in[3];
    const float* a_src1 = (const float*)d_in[4];
    const float* a_dst1 = (const float*)d_in[5];
    const float* b1     = (const float*)d_in[6];
    const float* W2     = (const float*)d_in[7];
    const float* a_src2 = (const float*)d_in[8];
    const float* a_dst2 = (const float*)d_in[9];
    const float* b2     = (const float*)d_in[10];
    const float* Wp     = (const float*)d_in[11];
    const float* bp     = (const float*)d_in[12];
    float*       out    = (float*)d_out;

    prep_kernel<<<(N_NODES + 255) / 256, 256>>>(ei_raw, b_raw);
    edges_count_kernel<<<(E_EDGES + 255) / 256, 256>>>(ei_raw);
    scan_kernel<<<1, 1024>>>();
    fill_kernel<<<(TOT_E + 255) / 256, 256>>>();

    gemm1_kernel<<<dim3((N_NODES + 127) / 128, 2), 256>>>(x, W1, a_src1, a_dst1);
    agg1_kernel<<<(N_NODES * 32 + 255) / 256, 256>>>(b1);

    gemm2_kernel<<<dim3((N_NODES + 127) / 128, 1), 256>>>(W2, a_src2, a_dst2);
    agg2_kernel<<<(N_NODES * 32 + 255) / 256, 256>>>(b2);

    pool_head_kernel<<<NGRAPH, 128>>>(Wp, bp, out);
}

// round 8
// speedup vs baseline: 1.2343x; 1.0820x over previous
#include <cuda_runtime.h>
#include <cuda_fp16.h>
#include <math.h>

#define N_NODES 20000
#define E_EDGES 640000
#define TOT_E   (E_EDGES + N_NODES)   // with self-loops
#define NGRAPH  64
#define F_IN    256
#define HID     128
#define HEADS   2
#define OUTF    10
#define NEG_SLOPE 0.2f

// ---------------- scratch (device globals; no allocation allowed) -----------
__device__ __align__(16) __half g_h1[(size_t)N_NODES * 256]; // layer1 feats (fp16)
__device__ __align__(16) __half g_h2[(size_t)N_NODES * 128]; // layer2 feats (fp16)
__device__ __align__(16) float g_out1[(size_t)N_NODES * 256]; // layer1 output (relu)
__device__ __align__(16) float g_out2[(size_t)N_NODES * 128]; // layer2 output
__device__ float g_al_s1[N_NODES * 2];
__device__ float g_al_d1[N_NODES * 2];
__device__ float g_al_s2[N_NODES];
__device__ float g_al_d2[N_NODES];
__device__ int   g_deg   [N_NODES];
__device__ int   g_off   [N_NODES + 1];
__device__ int   g_csr_src[TOT_E];
__device__ int   g_ei    [2 * E_EDGES];           // normalized int32 edge index
__device__ int   g_rank  [E_EDGES];               // per-edge rank within its dst
__device__ int   g_batch [N_NODES];               // normalized int32 batch

// ---------------- dtype detection helper -------------------------------------
// If edge data is int64 (values in [0, 2^31)), every odd int32 word is 0.
// For int32 uniform-random node ids, 256 consecutive odd words all zero has
// probability ~0. Computed from the EDGE buffer only.
__device__ __forceinline__ int detect_is64_block(const int* __restrict__ raw_e,
                                                 int* s_flag) {
    if (threadIdx.x == 0) {
        int any = 0;
#pragma unroll 8
        for (int i = 0; i < 256; i++) any |= raw_e[2 * i + 1];
        *s_flag = (any == 0) ? 1 : 0;
    }
    __syncthreads();
    return *s_flag;
}

// ---------------- kernel 0: zero degrees + convert batch ---------------------
__global__ void prep_kernel(const int* __restrict__ raw_e,
                            const int* __restrict__ raw_b) {
    __shared__ int s_flag;
    int is64 = detect_is64_block(raw_e, &s_flag);
    int i = blockIdx.x * blockDim.x + threadIdx.x;
    if (i < N_NODES) {
        g_deg[i] = 0;
        g_batch[i] = is64 ? raw_b[2 * i] : raw_b[i];
    }
}

// ---------------- kernel 1: convert edges + count degrees + capture rank -----
__global__ void edges_count_kernel(const int* __restrict__ raw_e) {
    __shared__ int s_flag;
    int is64 = detect_is64_block(raw_e, &s_flag);
    int i = blockIdx.x * blockDim.x + threadIdx.x;
    if (i < E_EDGES) {
        int src = is64 ? raw_e[2 * i] : raw_e[i];
        int dst = is64 ? raw_e[2 * (E_EDGES + i)] : raw_e[E_EDGES + i];
        g_ei[i] = src;
        g_ei[E_EDGES + i] = dst;
        g_rank[i] = atomicAdd(&g_deg[dst], 1);
    }
}

// ---------------- kernel 2: fast single-block scan ---------------------------
__global__ void scan_kernel() {
    __shared__ int sh[1024];
    int t = threadIdx.x;
    int base = t * 20;
    int vals[20];
    int tot = 0;
    if (t < 1000) {
#pragma unroll
        for (int k = 0; k < 20; k++) {
            vals[k] = g_deg[base + k] + 1;   // +1 self loop
            tot += vals[k];
        }
    }
    sh[t] = tot;
    __syncthreads();
#pragma unroll
    for (int ofs = 1; ofs < 1024; ofs <<= 1) {
        int add = (t >= ofs) ? sh[t - ofs] : 0;
        __syncthreads();
        sh[t] += add;
        __syncthreads();
    }
    int ex = sh[t] - tot;
    if (t < 1000) {
        int run = ex;
#pragma unroll
        for (int k = 0; k < 20; k++) {
            g_off[base + k] = run;
            run += vals[k];
        }
    }
    if (t == 0) g_off[N_NODES] = TOT_E;
}

// ---------------- kernel 3: CSR fill (atomic-free) ---------------------------
__global__ void fill_kernel() {
    int i = blockIdx.x * blockDim.x + threadIdx.x;
    if (i < E_EDGES) {
        int src = g_ei[i];
        int dst = g_ei[E_EDGES + i];
        g_csr_src[g_off[dst] + g_rank[i]] = src;
    } else if (i < TOT_E) {
        int n = i - E_EDGES;            // self loop goes last in its bucket
        g_csr_src[g_off[n] + g_deg[n]] = n;
    }
}

// ---------------- SGEMM + fp16 store + fused attention-logit epilogue --------
// C_half[M x NC] = fp16(A[M x K] @ B[NC x K]^T). BM=BN=128, BK=16, 256 thr,
// 8x8 microtile, register-prefetch double buffering. Logits computed from the
// exact fp32 accumulators (matching the reference's fp32 logit path).
template <int K, int NC, int HSTRIDE>
__device__ __forceinline__ void sgemm_logits_body(const float* __restrict__ A,
                                                  const float* __restrict__ B,
                                                  __half* __restrict__ C,
                                                  const float* __restrict__ a_s,
                                                  const float* __restrict__ a_d,
                                                  float* __restrict__ al_s,
                                                  float* __restrict__ al_d,
                                                  int M) {
    __shared__ float As[16][128];
    __shared__ float Bs[16][128];
    int tid = threadIdx.x;
    int bm = blockIdx.x * 128;
    int bn = blockIdx.y * 128;
    int h  = bn >> 7;
    int tx = tid & 15;
    int ty = tid >> 4;

    int rowA0 = tid >> 2,            c4A0 = (tid & 3) << 2;
    int rowA1 = (tid + 256) >> 2,    c4A1 = ((tid + 256) & 3) << 2;

    float acc[8][8];
#pragma unroll
    for (int i = 0; i < 8; i++)
#pragma unroll
        for (int j = 0; j < 8; j++) acc[i][j] = 0.f;

    auto ldA = [&](int k0, int row, int c4) -> float4 {
        int gr = bm + row;
        if (gr < M) return *reinterpret_cast<const float4*>(A + (size_t)gr * K + k0 + c4);
        return make_float4(0.f, 0.f, 0.f, 0.f);
    };
    auto ldB = [&](int k0, int row, int c4) -> float4 {
        int gn = bn + row;
        if (gn < NC) return *reinterpret_cast<const float4*>(B + (size_t)gn * K + k0 + c4);
        return make_float4(0.f, 0.f, 0.f, 0.f);
    };
    auto stTile = [&](float4 a0, float4 a1, float4 b0, float4 b1) {
        As[c4A0 + 0][rowA0] = a0.x; As[c4A0 + 1][rowA0] = a0.y;
        As[c4A0 + 2][rowA0] = a0.z; As[c4A0 + 3][rowA0] = a0.w;
        As[c4A1 + 0][rowA1] = a1.x; As[c4A1 + 1][rowA1] = a1.y;
        As[c4A1 + 2][rowA1] = a1.z; As[c4A1 + 3][rowA1] = a1.w;
        Bs[c4A0 + 0][rowA0] = b0.x; Bs[c4A0 + 1][rowA0] = b0.y;
        Bs[c4A0 + 2][rowA0] = b0.z; Bs[c4A0 + 3][rowA0] = b0.w;
        Bs[c4A1 + 0][rowA1] = b1.x; Bs[c4A1 + 1][rowA1] = b1.y;
        Bs[c4A1 + 2][rowA1] = b1.z; Bs[c4A1 + 3][rowA1] = b1.w;
    };

    {
        float4 a0 = ldA(0, rowA0, c4A0), a1 = ldA(0, rowA1, c4A1);
        float4 b0 = ldB(0, rowA0, c4A0), b1 = ldB(0, rowA1, c4A1);
        stTile(a0, a1, b0, b1);
    }
    __syncthreads();

    for (int k0 = 0; k0 < K; k0 += 16) {
        float4 na0, na1, nb0, nb1;
        bool has_next = (k0 + 16) < K;
        if (has_next) {
            na0 = ldA(k0 + 16, rowA0, c4A0); na1 = ldA(k0 + 16, rowA1, c4A1);
            nb0 = ldB(k0 + 16, rowA0, c4A0); nb1 = ldB(k0 + 16, rowA1, c4A1);
        }
#pragma unroll
        for (int kk = 0; kk < 16; kk++) {
            float a[8], b[8];
#pragma unroll
            for (int i = 0; i < 8; i++) a[i] = As[kk][ty * 8 + i];
#pragma unroll
            for (int j = 0; j < 8; j++) b[j] = Bs[kk][tx * 8 + j];
#pragma unroll
            for (int i = 0; i < 8; i++)
#pragma unroll
                for (int j = 0; j < 8; j++) acc[i][j] += a[i] * b[j];
        }
        __syncthreads();
        if (has_next) {
            stTile(na0, na1, nb0, nb1);
            __syncthreads();
        }
    }

    // store C tile as fp16 (8 cols = 4 half2 = one 16B store per row)
#pragma unroll
    for (int i = 0; i < 8; i++) {
        int gr = bm + ty * 8 + i;
        if (gr < M) {
            __half2 hv[4];
#pragma unroll
            for (int q = 0; q < 4; q++)
                hv[q] = __floats2half2_rn(acc[i][2 * q], acc[i][2 * q + 1]);
            int gc = bn + tx * 8;
            *reinterpret_cast<float4*>(C + (size_t)gr * NC + gc) =
                *reinterpret_cast<const float4*>(hv);
        }
    }

    // fused logits from exact fp32 accumulators
    float as_reg[8], ad_reg[8];
#pragma unroll
    for (int j = 0; j < 8; j++) {
        as_reg[j] = a_s[h * 128 + tx * 8 + j];
        ad_reg[j] = a_d[h * 128 + tx * 8 + j];
    }
#pragma unroll
    for (int i = 0; i < 8; i++) {
        float ps = 0.f, pd = 0.f;
#pragma unroll
        for (int j = 0; j < 8; j++) {
            ps += acc[i][j] * as_reg[j];
            pd += acc[i][j] * ad_reg[j];
        }
#pragma unroll
        for (int o = 8; o; o >>= 1) {
            ps += __shfl_xor_sync(0xffffffffu, ps, o);
            pd += __shfl_xor_sync(0xffffffffu, pd, o);
        }
        if (tx == 0) {
            int gr = bm + ty * 8 + i;
            if (gr < M) {
                al_s[gr * HSTRIDE + h] = ps;
                al_d[gr * HSTRIDE + h] = pd;
            }
        }
    }
}

__global__ void gemm1_kernel(const float* __restrict__ x, const float* __restrict__ W1,
                             const float* __restrict__ a_s, const float* __restrict__ a_d) {
    sgemm_logits_body<256, 256, 2>(x, W1, g_h1, a_s, a_d, g_al_s1, g_al_d1, N_NODES);
}
__global__ void gemm2_kernel(const float* __restrict__ W2,
                             const float* __restrict__ a_s, const float* __restrict__ a_d) {
    sgemm_logits_body<256, 128, 1>(g_out1, W2, g_h2, a_s, a_d, g_al_s2, g_al_d2, N_NODES);
}

// ---------------- aggregation layer 1: warp per node, fp16 gathers -----------
// Per edge: 1 CSR read, 3 shfls, ONE LDG.128 per lane covering all 256 fp16
// source features. Lanes 0-15 accumulate head0 channels (lane*8..lane*8+7),
// lanes 16-31 head1 channels. Single-pass softmax (bounded logits; shift-free
// exp is mathematically identical).
__global__ void agg1_kernel(const float* __restrict__ b1) {
    int w = (blockIdx.x * blockDim.x + threadIdx.x) >> 5;
    int lane = threadIdx.x & 31;
    if (w >= N_NODES) return;
    int beg = g_off[w], end = g_off[w + 1];
    float2 ald = *reinterpret_cast<const float2*>(&g_al_d1[w * 2]);

    float d0 = 0.f, d1 = 0.f;
    float acc[8];
#pragma unroll
    for (int k = 0; k < 8; k++) acc[k] = 0.f;

    for (int cbeg = beg; cbeg < end; cbeg += 32) {
        int i = cbeg + lane;
        float ex0 = 0.f, ex1 = 0.f; int s = 0;
        if (i < end) {
            s = g_csr_src[i];
            float2 als = *reinterpret_cast<const float2*>(&g_al_s1[s * 2]);
            float e0 = als.x + ald.x; e0 = (e0 > 0.f) ? e0 : e0 * NEG_SLOPE;
            float e1 = als.y + ald.y; e1 = (e1 > 0.f) ? e1 : e1 * NEG_SLOPE;
            ex0 = __expf(e0);
            ex1 = __expf(e1);
        }
        d0 += ex0; d1 += ex1;
        int cnt = min(32, end - cbeg);
        int j = 0;
        for (; j + 8 <= cnt; j += 8) {
#pragma unroll
            for (int u = 0; u < 8; u++) {
                int   sj = __shfl_sync(0xffffffffu, s,   j + u);
                float x0 = __shfl_sync(0xffffffffu, ex0, j + u);
                float x1 = __shfl_sync(0xffffffffu, ex1, j + u);
                float xw = (lane < 16) ? x0 : x1;
                float4 raw = reinterpret_cast<const float4*>(g_h1 + (size_t)sj * 256)[lane];
                const __half2* hp = reinterpret_cast<const __half2*>(&raw);
#pragma unroll
                for (int q = 0; q < 4; q++) {
                    float2 f = __half22float2(hp[q]);
                    acc[2 * q]     += xw * f.x;
                    acc[2 * q + 1] += xw * f.y;
                }
            }
        }
        for (; j < cnt; j++) {
            int   sj = __shfl_sync(0xffffffffu, s,   j);
            float x0 = __shfl_sync(0xffffffffu, ex0, j);
            float x1 = __shfl_sync(0xffffffffu, ex1, j);
            float xw = (lane < 16) ? x0 : x1;
            float4 raw = reinterpret_cast<const float4*>(g_h1 + (size_t)sj * 256)[lane];
            const __half2* hp = reinterpret_cast<const __half2*>(&raw);
#pragma unroll
            for (int q = 0; q < 4; q++) {
                float2 f = __half22float2(hp[q]);
                acc[2 * q]     += xw * f.x;
                acc[2 * q + 1] += xw * f.y;
            }
        }
    }
#pragma unroll
    for (int o = 16; o; o >>= 1) {
        d0 += __shfl_xor_sync(0xffffffffu, d0, o);
        d1 += __shfl_xor_sync(0xffffffffu, d1, o);
    }
    float inv = (lane < 16) ? (1.0f / d0) : (1.0f / d1);
    // lane covers global cols lane*8 .. lane*8+7
    const float4* bq = reinterpret_cast<const float4*>(b1 + lane * 8);
    float4 B0 = bq[0], B1 = bq[1];
    float4 o0, o1;
    o0.x = fmaxf(acc[0] * inv + B0.x, 0.f); o0.y = fmaxf(acc[1] * inv + B0.y, 0.f);
    o0.z = fmaxf(acc[2] * inv + B0.z, 0.f); o0.w = fmaxf(acc[3] * inv + B0.w, 0.f);
    o1.x = fmaxf(acc[4] * inv + B1.x, 0.f); o1.y = fmaxf(acc[5] * inv + B1.y, 0.f);
    o1.z = fmaxf(acc[6] * inv + B1.z, 0.f); o1.w = fmaxf(acc[7] * inv + B1.w, 0.f);
    float4* op = reinterpret_cast<float4*>(g_out1 + (size_t)w * 256 + lane * 8);
    op[0] = o0;
    op[1] = o1;
}

// ---------------- aggregation layer 2: warp per node, fp16 gathers -----------
// Per edge: one LDG.64 per lane (4 fp16 channels: lane*4..lane*4+3).
__global__ void agg2_kernel(const float* __restrict__ b2) {
    int w = (blockIdx.x * blockDim.x + threadIdx.x) >> 5;
    int lane = threadIdx.x & 31;
    if (w >= N_NODES) return;
    int beg = g_off[w], end = g_off[w + 1];
    float ald = g_al_d2[w];

    float d = 0.f;
    float4 A = make_float4(0.f, 0.f, 0.f, 0.f);
    for (int cbeg = beg; cbeg < end; cbeg += 32) {
        int i = cbeg + lane;
        float ex = 0.f; int s = 0;
        if (i < end) {
            s = g_csr_src[i];
            float e = g_al_s2[s] + ald;
            e = (e > 0.f) ? e : e * NEG_SLOPE;
            ex = __expf(e);
        }
        d += ex;
        int cnt = min(32, end - cbeg);
        int j = 0;
        for (; j + 8 <= cnt; j += 8) {
#pragma unroll
            for (int u = 0; u < 8; u++) {
                int   sj = __shfl_sync(0xffffffffu, s,  j + u);
                float xv = __shfl_sync(0xffffffffu, ex, j + u);
                float2 raw = reinterpret_cast<const float2*>(g_h2 + (size_t)sj * 128)[lane];
                const __half2* hp = reinterpret_cast<const __half2*>(&raw);
                float2 f0 = __half22float2(hp[0]);
                float2 f1 = __half22float2(hp[1]);
                A.x += xv * f0.x; A.y += xv * f0.y;
                A.z += xv * f1.x; A.w += xv * f1.y;
            }
        }
        for (; j < cnt; j++) {
            int   sj = __shfl_sync(0xffffffffu, s,  j);
            float xv = __shfl_sync(0xffffffffu, ex, j);
            float2 raw = reinterpret_cast<const float2*>(g_h2 + (size_t)sj * 128)[lane];
            const __half2* hp = reinterpret_cast<const __half2*>(&raw);
            float2 f0 = __half22float2(hp[0]);
            float2 f1 = __half22float2(hp[1]);
            A.x += xv * f0.x; A.y += xv * f0.y;
            A.z += xv * f1.x; A.w += xv * f1.y;
        }
    }
#pragma unroll
    for (int o = 16; o; o >>= 1) d += __shfl_xor_sync(0xffffffffu, d, o);
    float inv = 1.0f / d;
    // lane covers cols lane*4..lane*4+3
    float4 B = reinterpret_cast<const float4*>(b2)[lane];
    float4 o4;
    o4.x = A.x * inv + B.x; o4.y = A.y * inv + B.y;
    o4.z = A.z * inv + B.z; o4.w = A.w * inv + B.w;
    reinterpret_cast<float4*>(g_out2 + (size_t)w * 128)[lane] = o4;
}

// ---------------- mean pool per graph + prediction head ---------------------
__device__ __forceinline__ int lower_bound_i(const int* a, int n, int key) {
    int lo = 0, hi = n;
    while (lo < hi) {
        int mid = (lo + hi) >> 1;
        if (a[mid] < key) lo = mid + 1; else hi = mid;
    }
    return lo;
}

__global__ void pool_head_kernel(const float* __restrict__ Wp,
                                 const float* __restrict__ bp,
                                 float* __restrict__ out) {
    int g = blockIdx.x;
    __shared__ int s_beg, s_end;
    __shared__ float mean[128];
    if (threadIdx.x == 0) {
        s_beg = lower_bound_i(g_batch, N_NODES, g);
        s_end = lower_bound_i(g_batch, N_NODES, g + 1);
    }
    __syncthreads();
    int c = threadIdx.x;
    float acc = 0.f;
    for (int n = s_beg; n < s_end; n++) acc += g_out2[(size_t)n * 128 + c];
    float cnt = (float)max(s_end - s_beg, 1);
    mean[c] = acc / cnt;
    __syncthreads();
    if (c < OUTF) {
        float s = bp[c];
        const float* wr = Wp + c * 128;
#pragma unroll 8
        for (int k = 0; k < 128; k++) s += mean[k] * wr[k];
        out[g * OUTF + c] = s;
    }
}

// ---------------- launch -----------------------------------------------------
extern "C" void kernel_launch(void* const* d_in, const int* in_sizes, int n_in,
                              void* d_out, int out_size) {
    const float* x      = (const float*)d_in[0];
    const int*   ei_raw = (const int*)d_in[1];
    const int*   b_raw  = (const int*)d_in[2];
    const float* W1     = (const float*)d_in[3];
    const float* a_src1 = (const float*)d_in[4];
    const float* a_dst1 = (const float*)d_in[5];
    const float* b1     = (const float*)d_in[6];
    const float* W2     = (const float*)d_in[7];
    const float* a_src2 = (const float*)d_in[8];
    const float* a_dst2 = (const float*)d_in[9];
    const float* b2     = (const float*)d_in[10];
    const float* Wp     = (const float*)d_in[11];
    const float* bp     = (const float*)d_in[12];
    float*       out    = (float*)d_out;

    prep_kernel<<<(N_NODES + 255) / 256, 256>>>(ei_raw, b_raw);
    edges_count_kernel<<<(E_EDGES + 255) / 256, 256>>>(ei_raw);
    scan_kernel<<<1, 1024>>>();
    fill_kernel<<<(TOT_E + 255) / 256, 256>>>();

    gemm1_kernel<<<dim3((N_NODES + 127) / 128, 2), 256>>>(x, W1, a_src1, a_dst1);
    agg1_kernel<<<(N_NODES * 32 + 255) / 256, 256>>>(b1);

    gemm2_kernel<<<dim3((N_NODES + 127) / 128, 1), 256>>>(W2, a_src2, a_dst2);
    agg2_kernel<<<(N_NODES * 32 + 255) / 256, 256>>>(b2);

    pool_head_kernel<<<NGRAPH, 128>>>(Wp, bp, out);
}

// round 14
// speedup vs baseline: 2.0154x; 1.6329x over previous
#include <cuda_runtime.h>
#include <cuda_fp16.h>
#include <mma.h>
#include <math.h>
#include <cstdint>

using namespace nvcuda;

#define N_NODES 20000
#define E_EDGES 640000
#define TOT_E   (E_EDGES + N_NODES)
#define NGRAPH  64
#define OUTF    10
#define NEG_SLOPE 0.2f
#define XE  (N_NODES * 256)
#define W1E (256 * 256)
#define W2E (128 * 256)
#define CVT_TOTAL (XE + W1E + W2E)

__device__ __align__(16) __half g_xh   [(size_t)N_NODES * 256];
__device__ __align__(16) __half g_w1h  [W1E];
__device__ __align__(16) __half g_w2h  [W2E];
__device__ __align__(16) __half g_h1   [(size_t)N_NODES * 256];
__device__ __align__(16) __half g_out1h[(size_t)N_NODES * 256];
__device__ __align__(16) __half g_h2   [(size_t)N_NODES * 128];
__device__ __align__(16) float  g_out2 [(size_t)N_NODES * 128];
__device__ float g_al_s1[N_NODES * 2];
__device__ float g_al_d1[N_NODES * 2];
__device__ float g_al_s2[N_NODES];
__device__ float g_al_d2[N_NODES];
__device__ int g_deg[N_NODES];
__device__ int g_off[N_NODES + 1];
__device__ int g_csr_src[TOT_E];
__device__ int g_ei[2 * E_EDGES];
__device__ int g_rank[E_EDGES];
__device__ int g_batch[N_NODES];

__device__ __forceinline__ int detect64(const int* raw_e, int* s_flag) {
    if (threadIdx.x == 0) {
        int any = 0;
        for (int i = 0; i < 256; i++) any |= raw_e[2 * i + 1];
        *s_flag = (any == 0) ? 1 : 0;
    }
    __syncthreads();
    return *s_flag;
}

__global__ void prep_kernel(const int* raw_e, const int* raw_b) {
    __shared__ int s_flag;
    int is64 = detect64(raw_e, &s_flag);
    int i = blockIdx.x * blockDim.x + threadIdx.x;
    if (i < N_NODES) {
        g_deg[i] = 0;
        g_batch[i] = is64 ? raw_b[2 * i] : raw_b[i];
    }
}

__global__ void convert_kernel(const float* x, const float* W1, const float* W2) {
    int idx4 = (blockIdx.x * blockDim.x + threadIdx.x) * 4;
    if (idx4 >= CVT_TOTAL) return;
    const float* src;
    __half* dst;
    int off;
    if (idx4 < XE) { src = x; dst = g_xh; off = idx4; }
    else if (idx4 < XE + W1E) { src = W1; dst = g_w1h; off = idx4 - XE; }
    else { src = W2; dst = g_w2h; off = idx4 - XE - W1E; }
    float4 fv = *reinterpret_cast<const float4*>(src + off);
    __half2 h0 = __floats2half2_rn(fv.x, fv.y);
    __half2 h1 = __floats2half2_rn(fv.z, fv.w);
    uint2 pk;
    pk.x = *reinterpret_cast<unsigned int*>(&h0);
    pk.y = *reinterpret_cast<unsigned int*>(&h1);
    *reinterpret_cast<uint2*>(dst + off) = pk;
}

__global__ void edges_count_kernel(const int* raw_e) {
    __shared__ int s_flag;
    int is64 = detect64(raw_e, &s_flag);
    int i = blockIdx.x * blockDim.x + threadIdx.x;
    if (i < E_EDGES) {
        int es = is64 ? raw_e[2 * i] : raw_e[i];
        int ed = is64 ? raw_e[2 * (E_EDGES + i)] : raw_e[E_EDGES + i];
        g_ei[i] = es;
        g_ei[E_EDGES + i] = ed;
        g_rank[i] = atomicAdd(&g_deg[ed], 1);
    }
}

__global__ void scan_kernel() {
    __shared__ int sh[1024];
    int t = threadIdx.x;
    int base = t * 20;
    int vals[20];
    int tot = 0;
    if (t < 1000) {
        for (int k = 0; k < 20; k++) {
            vals[k] = g_deg[base + k] + 1;
            tot += vals[k];
        }
    }
    sh[t] = tot;
    __syncthreads();
    for (int ofs = 1; ofs < 1024; ofs <<= 1) {
        int add = (t >= ofs) ? sh[t - ofs] : 0;
        __syncthreads();
        sh[t] += add;
        __syncthreads();
    }
    int run = sh[t] - tot;
    if (t < 1000) {
        for (int k = 0; k < 20; k++) {
            g_off[base + k] = run;
            run += vals[k];
        }
    }
    if (t == 0) g_off[N_NODES] = TOT_E;
}

__global__ void fill_kernel() {
    int i = blockIdx.x * blockDim.x + threadIdx.x;
    if (i < E_EDGES) {
        g_csr_src[g_off[g_ei[E_EDGES + i]] + g_rank[i]] = g_ei[i];
    } else if (i < TOT_E) {
        int n = i - E_EDGES;
        g_csr_src[g_off[n] + g_deg[n]] = n;
    }
}

// WMMA GEMM: C_half[M x NC] = fp16(A_half[M x 256] @ B_half[NC x 256]^T),
// fp32 accumulate. Block 128x128, 8 warps (2M x 4N), warp tile 64x32
// (4x2 wmma 16x16x16 fragments), BK=16, register-prefetch.
template <int NC>
__device__ __forceinline__ void wmma_gemm_body(const __half* A, const __half* B,
                                               __half* C, int M) {
    const int K = 256;
    const int LDS_PAD = 24;
    __shared__ __align__(16) __half Am[128 * LDS_PAD];
    __shared__ __align__(16) __half Bm[128 * LDS_PAD];
    __shared__ __align__(16) float Cp[8][16 * 16];

    int tid = threadIdx.x;
    int lane = tid & 31;
    int wid = tid >> 5;
    int wm = wid & 1;
    int wn = wid >> 1;
    int bm = blockIdx.x * 128;
    int bn = blockIdx.y * 128;

    int lrow = tid >> 1;
    int lpart = (tid & 1) * 8;

    wmma::fragment<wmma::matrix_a, 16, 16, 16, __half, wmma::row_major> af[4];
    wmma::fragment<wmma::matrix_b, 16, 16, 16, __half, wmma::col_major> bf[2];
    wmma::fragment<wmma::accumulator, 16, 16, 16, float> cf[4][2];
#pragma unroll
    for (int mt = 0; mt < 4; mt++)
#pragma unroll
        for (int nt = 0; nt < 2; nt++) wmma::fill_fragment(cf[mt][nt], 0.f);

    uint4 z4 = make_uint4(0, 0, 0, 0);
    uint4 ra = z4;
    if (bm + lrow < M)
        ra = *reinterpret_cast<const uint4*>(A + (size_t)(bm + lrow) * K + lpart);
    uint4 rb = *reinterpret_cast<const uint4*>(B + (size_t)(bn + lrow) * K + lpart);

    for (int k0 = 0; k0 < K; k0 += 16) {
        *reinterpret_cast<uint4*>(Am + lrow * LDS_PAD + lpart) = ra;
        *reinterpret_cast<uint4*>(Bm + lrow * LDS_PAD + lpart) = rb;
        __syncthreads();
        if (k0 + 16 < K) {
            int kn = k0 + 16;
            ra = z4;
            if (bm + lrow < M)
                ra = *reinterpret_cast<const uint4*>(A + (size_t)(bm + lrow) * K + kn + lpart);
            rb = *reinterpret_cast<const uint4*>(B + (size_t)(bn + lrow) * K + kn + lpart);
        }
#pragma unroll
        for (int mt = 0; mt < 4; mt++)
            wmma::load_matrix_sync(af[mt], Am + (wm * 64 + mt * 16) * LDS_PAD, LDS_PAD);
#pragma unroll
        for (int nt = 0; nt < 2; nt++)
            wmma::load_matrix_sync(bf[nt], Bm + (wn * 32 + nt * 16) * LDS_PAD, LDS_PAD);
#pragma unroll
        for (int mt = 0; mt < 4; mt++)
#pragma unroll
            for (int nt = 0; nt < 2; nt++)
                wmma::mma_sync(cf[mt][nt], af[mt], bf[nt], cf[mt][nt]);
        __syncthreads();
    }

    // epilogue: stage each fragment through smem, convert to fp16, store
#pragma unroll
    for (int mt = 0; mt < 4; mt++) {
#pragma unroll
        for (int nt = 0; nt < 2; nt++) {
            wmma::store_matrix_sync(Cp[wid], cf[mt][nt], 16, wmma::mem_row_major);
            __syncwarp();
            int idx = lane * 8;
            int rr = idx >> 4;
            int cc = idx & 15;
            const float* pp = Cp[wid] + rr * 16 + cc;
            __half2 hv[4];
            hv[0] = __floats2half2_rn(pp[0], pp[1]);
            hv[1] = __floats2half2_rn(pp[2], pp[3]);
            hv[2] = __floats2half2_rn(pp[4], pp[5]);
            hv[3] = __floats2half2_rn(pp[6], pp[7]);
            int grow = bm + wm * 64 + mt * 16 + rr;
            int gcol = bn + wn * 32 + nt * 16 + cc;
            if (grow < M)
                *reinterpret_cast<uint4*>(C + (size_t)grow * NC + gcol) =
                    *reinterpret_cast<const uint4*>(hv);
            __syncwarp();
        }
    }
}

__global__ __launch_bounds__(256, 2) void gemm1_kernel() {
    wmma_gemm_body<256>(g_xh, g_w1h, g_h1, N_NODES);
}
__global__ __launch_bounds__(256, 2) void gemm2_kernel() {
    wmma_gemm_body<128>(g_out1h, g_w2h, g_h2, N_NODES);
}

// logits: warp per (node, head); h stored fp16, dots in fp32
__global__ void logits1_kernel(const float* a_s, const float* a_d) {
    int w = (blockIdx.x * blockDim.x + threadIdx.x) >> 5;
    int lane = threadIdx.x & 31;
    if (w >= N_NODES * 2) return;
    int n = w >> 1;
    int h = w & 1;
    const __half* hp = g_h1 + (size_t)n * 256 + h * 128 + lane * 4;
    uint2 raw = *reinterpret_cast<const uint2*>(hp);
    const __half2* h2p = reinterpret_cast<const __half2*>(&raw);
    float2 f0 = __half22float2(h2p[0]);
    float2 f1 = __half22float2(h2p[1]);
    int c = h * 128 + lane * 4;
    float ss = f0.x * a_s[c] + f0.y * a_s[c + 1] + f1.x * a_s[c + 2] + f1.y * a_s[c + 3];
    float sd = f0.x * a_d[c] + f0.y * a_d[c + 1] + f1.x * a_d[c + 2] + f1.y * a_d[c + 3];
    for (int o = 16; o; o >>= 1) {
        ss += __shfl_xor_sync(0xffffffffu, ss, o);
        sd += __shfl_xor_sync(0xffffffffu, sd, o);
    }
    if (lane == 0) {
        g_al_s1[n * 2 + h] = ss;
        g_al_d1[n * 2 + h] = sd;
    }
}

__global__ void logits2_kernel(const float* a_s, const float* a_d) {
    int w = (blockIdx.x * blockDim.x + threadIdx.x) >> 5;
    int lane = threadIdx.x & 31;
    if (w >= N_NODES) return;
    const __half* hp = g_h2 + (size_t)w * 128 + lane * 4;
    uint2 raw = *reinterpret_cast<const uint2*>(hp);
    const __half2* h2p = reinterpret_cast<const __half2*>(&raw);
    float2 f0 = __half22float2(h2p[0]);
    float2 f1 = __half22float2(h2p[1]);
    int c = lane * 4;
    float ss = f0.x * a_s[c] + f0.y * a_s[c + 1] + f1.x * a_s[c + 2] + f1.y * a_s[c + 3];
    float sd = f0.x * a_d[c] + f0.y * a_d[c + 1] + f1.x * a_d[c + 2] + f1.y * a_d[c + 3];
    for (int o = 16; o; o >>= 1) {
        ss += __shfl_xor_sync(0xffffffffu, ss, o);
        sd += __shfl_xor_sync(0xffffffffu, sd, o);
    }
    if (lane == 0) {
        g_al_s2[w] = ss;
        g_al_d2[w] = sd;
    }
}

__global__ void agg1_kernel(const float* b1) {
    int w = (blockIdx.x * blockDim.x + threadIdx.x) >> 5;
    int lane = threadIdx.x & 31;
    if (w >= N_NODES) return;
    int beg = g_off[w];
    int end = g_off[w + 1];
    float2 ald = *reinterpret_cast<const float2*>(&g_al_d1[w * 2]);

    float den0 = 0.f;
    float den1 = 0.f;
    float acc[8];
#pragma unroll
    for (int k = 0; k < 8; k++) acc[k] = 0.f;

    for (int cbeg = beg; cbeg < end; cbeg += 32) {
        int i = cbeg + lane;
        float ex0 = 0.f;
        float ex1 = 0.f;
        int s = 0;
        if (i < end) {
            s = g_csr_src[i];
            float2 als = *reinterpret_cast<const float2*>(&g_al_s1[s * 2]);
            float e0 = als.x + ald.x;
            float e1 = als.y + ald.y;
            e0 = (e0 > 0.f) ? e0 : e0 * NEG_SLOPE;
            e1 = (e1 > 0.f) ? e1 : e1 * NEG_SLOPE;
            ex0 = __expf(e0);
            ex1 = __expf(e1);
        }
        den0 += ex0;
        den1 += ex1;
        int cnt = min(32, end - cbeg);
        int j = 0;
        for (; j + 8 <= cnt; j += 8) {
#pragma unroll
            for (int u = 0; u < 8; u++) {
                int sj = __shfl_sync(0xffffffffu, s, j + u);
                float x0 = __shfl_sync(0xffffffffu, ex0, j + u);
                float x1 = __shfl_sync(0xffffffffu, ex1, j + u);
                float xw = (lane < 16) ? x0 : x1;
                float4 raw = reinterpret_cast<const float4*>(g_h1 + (size_t)sj * 256)[lane];
                const __half2* hp = reinterpret_cast<const __half2*>(&raw);
#pragma unroll
                for (int q = 0; q < 4; q++) {
                    float2 f = __half22float2(hp[q]);
                    acc[2 * q] += xw * f.x;
                    acc[2 * q + 1] += xw * f.y;
                }
            }
        }
        for (; j < cnt; j++) {
            int sj = __shfl_sync(0xffffffffu, s, j);
            float x0 = __shfl_sync(0xffffffffu, ex0, j);
            float x1 = __shfl_sync(0xffffffffu, ex1, j);
            float xw = (lane < 16) ? x0 : x1;
            float4 raw = reinterpret_cast<const float4*>(g_h1 + (size_t)sj * 256)[lane];
            const __half2* hp = reinterpret_cast<const __half2*>(&raw);
#pragma unroll
            for (int q = 0; q < 4; q++) {
                float2 f = __half22float2(hp[q]);
                acc[2 * q] += xw * f.x;
                acc[2 * q + 1] += xw * f.y;
            }
        }
    }
#pragma unroll
    for (int o = 16; o; o >>= 1) {
        den0 += __shfl_xor_sync(0xffffffffu, den0, o);
        den1 += __shfl_xor_sync(0xffffffffu, den1, o);
    }
    float inv = (lane < 16) ? (1.0f / den0) : (1.0f / den1);
    __half2 hv[4];
#pragma unroll
    for (int q = 0; q < 4; q++) {
        float c0 = fmaxf(acc[2 * q] * inv + b1[lane * 8 + 2 * q], 0.f);
        float c1 = fmaxf(acc[2 * q + 1] * inv + b1[lane * 8 + 2 * q + 1], 0.f);
        hv[q] = __floats2half2_rn(c0, c1);
    }
    *reinterpret_cast<uint4*>(g_out1h + (size_t)w * 256 + lane * 8) =
        *reinterpret_cast<const uint4*>(hv);
}

__global__ void agg2_kernel(const float* b2) {
    int w = (blockIdx.x * blockDim.x + threadIdx.x) >> 5;
    int lane = threadIdx.x & 31;
    if (w >= N_NODES) return;
    int beg = g_off[w];
    int end = g_off[w + 1];
    float ald = g_al_d2[w];

    float den = 0.f;
    float4 acc = make_float4(0.f, 0.f, 0.f, 0.f);
    for (int cbeg = beg; cbeg < end; cbeg += 32) {
        int i = cbeg + lane;
        float ex = 0.f;
        int s = 0;
        if (i < end) {
            s = g_csr_src[i];
            float e = g_al_s2[s] + ald;
            e = (e > 0.f) ? e : e * NEG_SLOPE;
            ex = __expf(e);
        }
        den += ex;
        int cnt = min(32, end - cbeg);
        int j = 0;
        for (; j + 8 <= cnt; j += 8) {
#pragma unroll
            for (int u = 0; u < 8; u++) {
                int sj = __shfl_sync(0xffffffffu, s, j + u);
                float xv = __shfl_sync(0xffffffffu, ex, j + u);
                float2 raw = reinterpret_cast<const float2*>(g_h2 + (size_t)sj * 128)[lane];
                const __half2* hp = reinterpret_cast<const __half2*>(&raw);
                float2 f0 = __half22float2(hp[0]);
                float2 f1 = __half22float2(hp[1]);
                acc.x += xv * f0.x;
                acc.y += xv * f0.y;
                acc.z += xv * f1.x;
                acc.w += xv * f1.y;
            }
        }
        for (; j < cnt; j++) {
            int sj = __shfl_sync(0xffffffffu, s, j);
            float xv = __shfl_sync(0xffffffffu, ex, j);
            float2 raw = reinterpret_cast<const float2*>(g_h2 + (size_t)sj * 128)[lane];
            const __half2* hp = reinterpret_cast<const __half2*>(&raw);
            float2 f0 = __half22float2(hp[0]);
            float2 f1 = __half22float2(hp[1]);
            acc.x += xv * f0.x;
            acc.y += xv * f0.y;
            acc.z += xv * f1.x;
            acc.w += xv * f1.y;
        }
    }
#pragma unroll
    for (int o = 16; o; o >>= 1) den += __shfl_xor_sync(0xffffffffu, den, o);
    float inv = 1.0f / den;
    float4 bv = reinterpret_cast<const float4*>(b2)[lane];
    float4 ov = make_float4(acc.x * inv + bv.x, acc.y * inv + bv.y,
                            acc.z * inv + bv.z, acc.w * inv + bv.w);
    reinterpret_cast<float4*>(g_out2 + (size_t)w * 128)[lane] = ov;
}

__device__ __forceinline__ int lbound(const int* a, int n, int key) {
    int lo = 0;
    int hi = n;
    while (lo < hi) {
        int mid = (lo + hi) >> 1;
        if (a[mid] < key) lo = mid + 1; else hi = mid;
    }
    return lo;
}

__global__ void pool_head_kernel(const float* Wp, const float* bp, float* out) {
    int g = blockIdx.x;
    __shared__ int s_beg;
    __shared__ int s_end;
    __shared__ float mean[128];
    if (threadIdx.x == 0) {
        s_beg = lbound(g_batch, N_NODES, g);
        s_end = lbound(g_batch, N_NODES, g + 1);
    }
    __syncthreads();
    int c = threadIdx.x;
    float acc = 0.f;
    for (int n = s_beg; n < s_end; n++) acc += g_out2[(size_t)n * 128 + c];
    float cnt = (float)max(s_end - s_beg, 1);
    mean[c] = acc / cnt;
    __syncthreads();
    if (c < OUTF) {
        float s = bp[c];
        const float* wr = Wp + c * 128;
        for (int k = 0; k < 128; k++) s += mean[k] * wr[k];
        out[g * OUTF + c] = s;
    }
}

extern "C" void kernel_launch(void* const* d_in, const int* in_sizes, int n_in,
                              void* d_out, int out_size) {
    const float* x      = (const float*)d_in[0];
    const int*   ei_raw = (const int*)d_in[1];
    const int*   b_raw  = (const int*)d_in[2];
    const float* W1     = (const float*)d_in[3];
    const float* a_src1 = (const float*)d_in[4];
    const float* a_dst1 = (const float*)d_in[5];
    const float* b1     = (const float*)d_in[6];
    const float* W2     = (const float*)d_in[7];
    const float* a_src2 = (const float*)d_in[8];
    const float* a_dst2 = (const float*)d_in[9];
    const float* b2     = (const float*)d_in[10];
    const float* Wp     = (const float*)d_in[11];
    const float* bp     = (const float*)d_in[12];
    float*       out    = (float*)d_out;

    prep_kernel<<<(N_NODES + 255) / 256, 256>>>(ei_raw, b_raw);
    convert_kernel<<<(CVT_TOTAL / 4 + 255) / 256, 256>>>(x, W1, W2);
    edges_count_kernel<<<(E_EDGES + 255) / 256, 256>>>(ei_raw);
    scan_kernel<<<1, 1024>>>();
    fill_kernel<<<(TOT_E + 255) / 256, 256>>>();

    gemm1_kernel<<<dim3((N_NODES + 127) / 128, 2), 256>>>();
    logits1_kernel<<<(N_NODES * 2 * 32 + 255) / 256, 256>>>(a_src1, a_dst1);
    agg1_kernel<<<(N_NODES * 32 + 255) / 256, 256>>>(b1);

    gemm2_kernel<<<dim3((N_NODES + 127) / 128, 1), 256>>>();
    logits2_kernel<<<(N_NODES * 32 + 255) / 256, 256>>>(a_src2, a_dst2);
    agg2_kernel<<<(N_NODES * 32 + 255) / 256, 256>>>(b2);

    pool_head_kernel<<<NGRAPH, 128>>>(Wp, bp, out);
}

// round 15
// speedup vs baseline: 2.1589x; 1.0712x over previous
#include <cuda_runtime.h>
#include <cuda_fp16.h>
#include <mma.h>
#include <math.h>
#include <cstdint>

using namespace nvcuda;

#define N_NODES 20000
#define E_EDGES 640000
#define TOT_E   (E_EDGES + N_NODES)
#define NGRAPH  64
#define OUTF    10
#define NEG_SLOPE 0.2f
#define XE  (N_NODES * 256)
#define W1E (256 * 256)
#define W2E (128 * 256)
#define CVT_TOTAL (XE + W1E + W2E)
#define CVT4 ((CVT_TOTAL + 3) / 4)

__device__ __align__(16) __half g_xh   [(size_t)N_NODES * 256];
__device__ __align__(16) __half g_w1h  [W1E];
__device__ __align__(16) __half g_w2h  [W2E];
__device__ __align__(16) __half g_h1   [(size_t)N_NODES * 256];
__device__ __align__(16) __half g_out1h[(size_t)N_NODES * 256];
__device__ __align__(16) __half g_h2   [(size_t)N_NODES * 128];
__device__ __align__(16) float  g_out2 [(size_t)N_NODES * 128];
__device__ float g_al_s1[N_NODES * 2];
__device__ float g_al_d1[N_NODES * 2];
__device__ float g_al_s2[N_NODES];
__device__ float g_al_d2[N_NODES];
__device__ int g_deg[N_NODES];
__device__ int g_off[N_NODES + 1];
__device__ int g_csr_src[TOT_E];
__device__ int g_ei[2 * E_EDGES];
__device__ int g_rank[E_EDGES];
__device__ int g_batch[N_NODES];

__device__ __forceinline__ int detect64(const int* raw_e, int* s_flag) {
    if (threadIdx.x == 0) {
        int any = 0;
        for (int i = 0; i < 256; i++) any |= raw_e[2 * i + 1];
        *s_flag = (any == 0) ? 1 : 0;
    }
    __syncthreads();
    return *s_flag;
}

// merged: batch convert + edge convert/count/rank + fp32->fp16 conversion.
// g_deg is zeroed by cudaMemsetAsync BEFORE this kernel (stream-ordered).
__global__ void prep_all_kernel(const int* raw_e, const int* raw_b,
                                const float* x, const float* W1, const float* W2) {
    __shared__ int s_flag;
    int is64 = detect64(raw_e, &s_flag);
    int gi = blockIdx.x * blockDim.x + threadIdx.x;

    if (gi < N_NODES)
        g_batch[gi] = is64 ? raw_b[2 * gi] : raw_b[gi];

    if (gi < E_EDGES) {
        int es = is64 ? raw_e[2 * gi] : raw_e[gi];
        int ed = is64 ? raw_e[2 * (E_EDGES + gi)] : raw_e[E_EDGES + gi];
        g_ei[gi] = es;
        g_ei[E_EDGES + gi] = ed;
        g_rank[gi] = atomicAdd(&g_deg[ed], 1);
    }

    if (gi < CVT4) {
        int idx4 = gi * 4;
        const float* src;
        __half* dst;
        int off;
        if (idx4 < XE) { src = x; dst = g_xh; off = idx4; }
        else if (idx4 < XE + W1E) { src = W1; dst = g_w1h; off = idx4 - XE; }
        else { src = W2; dst = g_w2h; off = idx4 - XE - W1E; }
        float4 fv = *reinterpret_cast<const float4*>(src + off);
        __half2 h0 = __floats2half2_rn(fv.x, fv.y);
        __half2 h1 = __floats2half2_rn(fv.z, fv.w);
        uint2 pk;
        pk.x = *reinterpret_cast<unsigned int*>(&h0);
        pk.y = *reinterpret_cast<unsigned int*>(&h1);
        *reinterpret_cast<uint2*>(dst + off) = pk;
    }
}

// coalesced warp-scan: 32 warps x 640-element contiguous segments.
__global__ void scan_kernel() {
    __shared__ int wtot[32];
    __shared__ int woff[32];
    int lane = threadIdx.x & 31;
    int w = threadIdx.x >> 5;
    int base = w * 640;

    // pass 1: warp segment total (coalesced)
    int sum = 0;
    for (int k = 0; k < 20; k++) {
        int e = base + k * 32 + lane;
        sum += (e < N_NODES) ? (g_deg[e] + 1) : 0;
    }
    for (int o = 16; o; o >>= 1) sum += __shfl_xor_sync(0xffffffffu, sum, o);
    if (lane == 0) wtot[w] = sum;
    __syncthreads();

    // warp 0 scans the 32 totals
    if (w == 0) {
        int v = wtot[lane];
        int s = v;
        for (int o = 1; o < 32; o <<= 1) {
            int t = __shfl_up_sync(0xffffffffu, s, o);
            if (lane >= o) s += t;
        }
        woff[lane] = s - v;
    }
    __syncthreads();

    // pass 2: emit exclusive offsets (reads are L1/L2 hot)
    int carry = woff[w];
    for (int k = 0; k < 20; k++) {
        int e = base + k * 32 + lane;
        int v = (e < N_NODES) ? (g_deg[e] + 1) : 0;
        int s = v;
        for (int o = 1; o < 32; o <<= 1) {
            int t = __shfl_up_sync(0xffffffffu, s, o);
            if (lane >= o) s += t;
        }
        if (e < N_NODES) g_off[e] = carry + s - v;
        carry += __shfl_sync(0xffffffffu, s, 31);
    }
    if (threadIdx.x == 0) g_off[N_NODES] = TOT_E;
}

__global__ void fill_kernel() {
    int i = blockIdx.x * blockDim.x + threadIdx.x;
    if (i < E_EDGES) {
        g_csr_src[g_off[g_ei[E_EDGES + i]] + g_rank[i]] = g_ei[i];
    } else if (i < TOT_E) {
        int n = i - E_EDGES;
        g_csr_src[g_off[n] + g_deg[n]] = n;
    }
}

// WMMA GEMM: C_half[M x NC] = fp16(A_half[M x 256] @ B_half[NC x 256]^T),
// fp32 accumulate. Block 128x128, 8 warps (2M x 4N), warp tile 64x32,
// BK=16, register-prefetch.
template <int NC>
__device__ __forceinline__ void wmma_gemm_body(const __half* A, const __half* B,
                                               __half* C, int M) {
    const int K = 256;
    const int LDS_PAD = 24;
    __shared__ __align__(16) __half Am[128 * LDS_PAD];
    __shared__ __align__(16) __half Bm[128 * LDS_PAD];
    __shared__ __align__(16) float Cp[8][16 * 16];

    int tid = threadIdx.x;
    int lane = tid & 31;
    int wid = tid >> 5;
    int wm = wid & 1;
    int wn = wid >> 1;
    int bm = blockIdx.x * 128;
    int bn = blockIdx.y * 128;

    int lrow = tid >> 1;
    int lpart = (tid & 1) * 8;

    wmma::fragment<wmma::matrix_a, 16, 16, 16, __half, wmma::row_major> af[4];
    wmma::fragment<wmma::matrix_b, 16, 16, 16, __half, wmma::col_major> bf[2];
    wmma::fragment<wmma::accumulator, 16, 16, 16, float> cf[4][2];
#pragma unroll
    for (int mt = 0; mt < 4; mt++)
#pragma unroll
        for (int nt = 0; nt < 2; nt++) wmma::fill_fragment(cf[mt][nt], 0.f);

    uint4 z4 = make_uint4(0, 0, 0, 0);
    uint4 ra = z4;
    if (bm + lrow < M)
        ra = *reinterpret_cast<const uint4*>(A + (size_t)(bm + lrow) * K + lpart);
    uint4 rb = *reinterpret_cast<const uint4*>(B + (size_t)(bn + lrow) * K + lpart);

    for (int k0 = 0; k0 < K; k0 += 16) {
        *reinterpret_cast<uint4*>(Am + lrow * LDS_PAD + lpart) = ra;
        *reinterpret_cast<uint4*>(Bm + lrow * LDS_PAD + lpart) = rb;
        __syncthreads();
        if (k0 + 16 < K) {
            int kn = k0 + 16;
            ra = z4;
            if (bm + lrow < M)
                ra = *reinterpret_cast<const uint4*>(A + (size_t)(bm + lrow) * K + kn + lpart);
            rb = *reinterpret_cast<const uint4*>(B + (size_t)(bn + lrow) * K + kn + lpart);
        }
#pragma unroll
        for (int mt = 0; mt < 4; mt++)
            wmma::load_matrix_sync(af[mt], Am + (wm * 64 + mt * 16) * LDS_PAD, LDS_PAD);
#pragma unroll
        for (int nt = 0; nt < 2; nt++)
            wmma::load_matrix_sync(bf[nt], Bm + (wn * 32 + nt * 16) * LDS_PAD, LDS_PAD);
#pragma unroll
        for (int mt = 0; mt < 4; mt++)
#pragma unroll
            for (int nt = 0; nt < 2; nt++)
                wmma::mma_sync(cf[mt][nt], af[mt], bf[nt], cf[mt][nt]);
        __syncthreads();
    }

#pragma unroll
    for (int mt = 0; mt < 4; mt++) {
#pragma unroll
        for (int nt = 0; nt < 2; nt++) {
            wmma::store_matrix_sync(Cp[wid], cf[mt][nt], 16, wmma::mem_row_major);
            __syncwarp();
            int idx = lane * 8;
            int rr = idx >> 4;
            int cc = idx & 15;
            const float* pp = Cp[wid] + rr * 16 + cc;
            __half2 hv[4];
            hv[0] = __floats2half2_rn(pp[0], pp[1]);
            hv[1] = __floats2half2_rn(pp[2], pp[3]);
            hv[2] = __floats2half2_rn(pp[4], pp[5]);
            hv[3] = __floats2half2_rn(pp[6], pp[7]);
            int grow = bm + wm * 64 + mt * 16 + rr;
            int gcol = bn + wn * 32 + nt * 16 + cc;
            if (grow < M)
                *reinterpret_cast<uint4*>(C + (size_t)grow * NC + gcol) =
                    *reinterpret_cast<const uint4*>(hv);
            __syncwarp();
        }
    }
}

__global__ __launch_bounds__(256, 2) void gemm1_kernel() {
    wmma_gemm_body<256>(g_xh, g_w1h, g_h1, N_NODES);
}
__global__ __launch_bounds__(256, 2) void gemm2_kernel() {
    wmma_gemm_body<128>(g_out1h, g_w2h, g_h2, N_NODES);
}

__global__ void logits1_kernel(const float* a_s, const float* a_d) {
    int w = (blockIdx.x * blockDim.x + threadIdx.x) >> 5;
    int lane = threadIdx.x & 31;
    if (w >= N_NODES * 2) return;
    int n = w >> 1;
    int h = w & 1;
    const __half* hp = g_h1 + (size_t)n * 256 + h * 128 + lane * 4;
    uint2 raw = *reinterpret_cast<const uint2*>(hp);
    const __half2* h2p = reinterpret_cast<const __half2*>(&raw);
    float2 f0 = __half22float2(h2p[0]);
    float2 f1 = __half22float2(h2p[1]);
    int c = h * 128 + lane * 4;
    float ss = f0.x * a_s[c] + f0.y * a_s[c + 1] + f1.x * a_s[c + 2] + f1.y * a_s[c + 3];
    float sd = f0.x * a_d[c] + f0.y * a_d[c + 1] + f1.x * a_d[c + 2] + f1.y * a_d[c + 3];
    for (int o = 16; o; o >>= 1) {
        ss += __shfl_xor_sync(0xffffffffu, ss, o);
        sd += __shfl_xor_sync(0xffffffffu, sd, o);
    }
    if (lane == 0) {
        g_al_s1[n * 2 + h] = ss;
        g_al_d1[n * 2 + h] = sd;
    }
}

__global__ void logits2_kernel(const float* a_s, const float* a_d) {
    int w = (blockIdx.x * blockDim.x + threadIdx.x) >> 5;
    int lane = threadIdx.x & 31;
    if (w >= N_NODES) return;
    const __half* hp = g_h2 + (size_t)w * 128 + lane * 4;
    uint2 raw = *reinterpret_cast<const uint2*>(hp);
    const __half2* h2p = reinterpret_cast<const __half2*>(&raw);
    float2 f0 = __half22float2(h2p[0]);
    float2 f1 = __half22float2(h2p[1]);
    int c = lane * 4;
    float ss = f0.x * a_s[c] + f0.y * a_s[c + 1] + f1.x * a_s[c + 2] + f1.y * a_s[c + 3];
    float sd = f0.x * a_d[c] + f0.y * a_d[c + 1] + f1.x * a_d[c + 2] + f1.y * a_d[c + 3];
    for (int o = 16; o; o >>= 1) {
        ss += __shfl_xor_sync(0xffffffffu, ss, o);
        sd += __shfl_xor_sync(0xffffffffu, sd, o);
    }
    if (lane == 0) {
        g_al_s2[w] = ss;
        g_al_d2[w] = sd;
    }
}

__global__ void agg1_kernel(const float* b1) {
    int w = (blockIdx.x * blockDim.x + threadIdx.x) >> 5;
    int lane = threadIdx.x & 31;
    if (w >= N_NODES) return;
    int beg = g_off[w];
    int end = g_off[w + 1];
    float2 ald = *reinterpret_cast<const float2*>(&g_al_d1[w * 2]);

    float den0 = 0.f;
    float den1 = 0.f;
    float acc[8];
#pragma unroll
    for (int k = 0; k < 8; k++) acc[k] = 0.f;

    for (int cbeg = beg; cbeg < end; cbeg += 32) {
        int i = cbeg + lane;
        float ex0 = 0.f;
        float ex1 = 0.f;
        int s = 0;
        if (i < end) {
            s = g_csr_src[i];
            float2 als = *reinterpret_cast<const float2*>(&g_al_s1[s * 2]);
            float e0 = als.x + ald.x;
            float e1 = als.y + ald.y;
            e0 = (e0 > 0.f) ? e0 : e0 * NEG_SLOPE;
            e1 = (e1 > 0.f) ? e1 : e1 * NEG_SLOPE;
            ex0 = __expf(e0);
            ex1 = __expf(e1);
        }
        den0 += ex0;
        den1 += ex1;
        int cnt = min(32, end - cbeg);
        int j = 0;
        for (; j + 8 <= cnt; j += 8) {
#pragma unroll
            for (int u = 0; u < 8; u++) {
                int sj = __shfl_sync(0xffffffffu, s, j + u);
                float x0 = __shfl_sync(0xffffffffu, ex0, j + u);
                float x1 = __shfl_sync(0xffffffffu, ex1, j + u);
                float xw = (lane < 16) ? x0 : x1;
                float4 raw = reinterpret_cast<const float4*>(g_h1 + (size_t)sj * 256)[lane];
                const __half2* hp = reinterpret_cast<const __half2*>(&raw);
#pragma unroll
                for (int q = 0; q < 4; q++) {
                    float2 f = __half22float2(hp[q]);
                    acc[2 * q] += xw * f.x;
                    acc[2 * q + 1] += xw * f.y;
                }
            }
        }
        for (; j < cnt; j++) {
            int sj = __shfl_sync(0xffffffffu, s, j);
            float x0 = __shfl_sync(0xffffffffu, ex0, j);
            float x1 = __shfl_sync(0xffffffffu, ex1, j);
            float xw = (lane < 16) ? x0 : x1;
            float4 raw = reinterpret_cast<const float4*>(g_h1 + (size_t)sj * 256)[lane];
            const __half2* hp = reinterpret_cast<const __half2*>(&raw);
#pragma unroll
            for (int q = 0; q < 4; q++) {
                float2 f = __half22float2(hp[q]);
                acc[2 * q] += xw * f.x;
                acc[2 * q + 1] += xw * f.y;
            }
        }
    }
#pragma unroll
    for (int o = 16; o; o >>= 1) {
        den0 += __shfl_xor_sync(0xffffffffu, den0, o);
        den1 += __shfl_xor_sync(0xffffffffu, den1, o);
    }
    float inv = (lane < 16) ? (1.0f / den0) : (1.0f / den1);
    __half2 hv[4];
#pragma unroll
    for (int q = 0; q < 4; q++) {
        float c0 = fmaxf(acc[2 * q] * inv + b1[lane * 8 + 2 * q], 0.f);
        float c1 = fmaxf(acc[2 * q + 1] * inv + b1[lane * 8 + 2 * q + 1], 0.f);
        hv[q] = __floats2half2_rn(c0, c1);
    }
    *reinterpret_cast<uint4*>(g_out1h + (size_t)w * 256 + lane * 8) =
        *reinterpret_cast<const uint4*>(hv);
}

__global__ void agg2_kernel(const float* b2) {
    int w = (blockIdx.x * blockDim.x + threadIdx.x) >> 5;
    int lane = threadIdx.x & 31;
    if (w >= N_NODES) return;
    int beg = g_off[w];
    int end = g_off[w + 1];
    float ald = g_al_d2[w];

    float den = 0.f;
    float4 acc = make_float4(0.f, 0.f, 0.f, 0.f);
    for (int cbeg = beg; cbeg < end; cbeg += 32) {
        int i = cbeg + lane;
        float ex = 0.f;
        int s = 0;
        if (i < end) {
            s = g_csr_src[i];
            float e = g_al_s2[s] + ald;
            e = (e > 0.f) ? e : e * NEG_SLOPE;
            ex = __expf(e);
        }
        den += ex;
        int cnt = min(32, end - cbeg);
        int j = 0;
        for (; j + 8 <= cnt; j += 8) {
#pragma unroll
            for (int u = 0; u < 8; u++) {
                int sj = __shfl_sync(0xffffffffu, s, j + u);
                float xv = __shfl_sync(0xffffffffu, ex, j + u);
                float2 raw = reinterpret_cast<const float2*>(g_h2 + (size_t)sj * 128)[lane];
                const __half2* hp = reinterpret_cast<const __half2*>(&raw);
                float2 f0 = __half22float2(hp[0]);
                float2 f1 = __half22float2(hp[1]);
                acc.x += xv * f0.x;
                acc.y += xv * f0.y;
                acc.z += xv * f1.x;
                acc.w += xv * f1.y;
            }
        }
        for (; j < cnt; j++) {
            int sj = __shfl_sync(0xffffffffu, s, j);
            float xv = __shfl_sync(0xffffffffu, ex, j);
            float2 raw = reinterpret_cast<const float2*>(g_h2 + (size_t)sj * 128)[lane];
            const __half2* hp = reinterpret_cast<const __half2*>(&raw);
            float2 f0 = __half22float2(hp[0]);
            float2 f1 = __half22float2(hp[1]);
            acc.x += xv * f0.x;
            acc.y += xv * f0.y;
            acc.z += xv * f1.x;
            acc.w += xv * f1.y;
        }
    }
#pragma unroll
    for (int o = 16; o; o >>= 1) den += __shfl_xor_sync(0xffffffffu, den, o);
    float inv = 1.0f / den;
    float4 bv = reinterpret_cast<const float4*>(b2)[lane];
    float4 ov = make_float4(acc.x * inv + bv.x, acc.y * inv + bv.y,
                            acc.z * inv + bv.z, acc.w * inv + bv.w);
    reinterpret_cast<float4*>(g_out2 + (size_t)w * 128)[lane] = ov;
}

__device__ __forceinline__ int lbound(const int* a, int n, int key) {
    int lo = 0;
    int hi = n;
    while (lo < hi) {
        int mid = (lo + hi) >> 1;
        if (a[mid] < key) lo = mid + 1; else hi = mid;
    }
    return lo;
}

__global__ void pool_head_kernel(const float* Wp, const float* bp, float* out) {
    int g = blockIdx.x;
    __shared__ int s_beg;
    __shared__ int s_end;
    __shared__ float mean[128];
    if (threadIdx.x == 0) {
        s_beg = lbound(g_batch, N_NODES, g);
        s_end = lbound(g_batch, N_NODES, g + 1);
    }
    __syncthreads();
    int c = threadIdx.x;
    float acc = 0.f;
    for (int n = s_beg; n < s_end; n++) acc += g_out2[(size_t)n * 128 + c];
    float cnt = (float)max(s_end - s_beg, 1);
    mean[c] = acc / cnt;
    __syncthreads();
    if (c < OUTF) {
        float s = bp[c];
        const float* wr = Wp + c * 128;
        for (int k = 0; k < 128; k++) s += mean[k] * wr[k];
        out[g * OUTF + c] = s;
    }
}

extern "C" void kernel_launch(void* const* d_in, const int* in_sizes, int n_in,
                              void* d_out, int out_size) {
    const float* x      = (const float*)d_in[0];
    const int*   ei_raw = (const int*)d_in[1];
    const int*   b_raw  = (const int*)d_in[2];
    const float* W1     = (const float*)d_in[3];
    const float* a_src1 = (const float*)d_in[4];
    const float* a_dst1 = (const float*)d_in[5];
    const float* b1     = (const float*)d_in[6];
    const float* W2     = (const float*)d_in[7];
    const float* a_src2 = (const float*)d_in[8];
    const float* a_dst2 = (const float*)d_in[9];
    const float* b2     = (const float*)d_in[10];
    const float* Wp     = (const float*)d_in[11];
    const float* bp     = (const float*)d_in[12];
    float*       out    = (float*)d_out;

    void* degp = 0;
    cudaGetSymbolAddress(&degp, g_deg);
    cudaMemsetAsync(degp, 0, N_NODES * sizeof(int));

    prep_all_kernel<<<(CVT4 + 255) / 256, 256>>>(ei_raw, b_raw, x, W1, W2);
    scan_kernel<<<1, 1024>>>();
    fill_kernel<<<(TOT_E + 255) / 256, 256>>>();

    gemm1_kernel<<<dim3((N_NODES + 127) / 128, 2), 256>>>();
    logits1_kernel<<<(N_NODES * 2 * 32 + 255) / 256, 256>>>(a_src1, a_dst1);
    agg1_kernel<<<(N_NODES * 32 + 255) / 256, 256>>>(b1);

    gemm2_kernel<<<dim3((N_NODES + 127) / 128, 1), 256>>>();
    logits2_kernel<<<(N_NODES * 32 + 255) / 256, 256>>>(a_src2, a_dst2);
    agg2_kernel<<<(N_NODES * 32 + 255) / 256, 256>>>(b2);

    pool_head_kernel<<<NGRAPH, 128>>>(Wp, bp, out);
}